// round 2
// baseline (speedup 1.0000x reference)
#include <cuda_runtime.h>
#include <cuda_bf16.h>
#include <cstdint>
#include <math.h>

// ---------------- problem constants ----------------
#define BATCH    16
#define NPTS     4096
#define CFEAT    64
#define SPOINT   1024
#define KSAMP    32
#define CIN      67
#define MROWS    (BATCH*SPOINT*KSAMP)      // 524288
#define NGROUP   (BATCH*SPOINT)            // 16384
#define NBLK     (MROWS/128)               // 4096
#define OUT_XYZ_ELEMS (BATCH*SPOINT*3)     // 49152

// ---------------- device scratch (no allocs allowed) ----------------
__device__ int   g_ballidx[MROWS];
__device__ float g_h0[(size_t)MROWS*64];
__device__ float g_h1[(size_t)MROWS*64];
__device__ float g_gmax[(size_t)NGROUP*128];
__device__ float g_gmin[(size_t)NGROUP*128];
__device__ float g_psum[NBLK*128];
__device__ float g_psq [NBLK*128];
__device__ float g_scale[3][128];
__device__ float g_shift[3][128];

// =====================================================================
// 1) Farthest point sampling. One block per batch, 1024 threads, 4 pts/thread.
//    Exact lowest-index tie-break argmax (matches jnp.argmax).
//    Writes new_xyz directly into d_out[0 .. 49152).
// =====================================================================
__global__ void fps_kernel(const float* __restrict__ xyz, float* __restrict__ out_xyz)
{
    extern __shared__ float sh[];            // sx[4096] sy[4096] sz[4096]
    float* sx = sh;
    float* sy = sh + NPTS;
    float* sz = sh + 2*NPTS;
    __shared__ float    wv[32];
    __shared__ unsigned wi[32];
    __shared__ int      sfar;

    const int b = blockIdx.x, t = threadIdx.x;
    const int lane = t & 31, warp = t >> 5;
    const float* base = xyz + (size_t)b*NPTS*3;

    float dist[4];
#pragma unroll
    for (int k = 0; k < 4; k++) {
        int p = t + k*1024;
        sx[p] = base[p*3+0]; sy[p] = base[p*3+1]; sz[p] = base[p*3+2];
        dist[k] = 1e10f;
    }
    __syncthreads();

    int far_ = 0;
    float* o = out_xyz + (size_t)b*SPOINT*3;

    for (int i = 0; i < SPOINT; i++) {
        float cx = sx[far_], cy = sy[far_], cz = sz[far_];
        if (t == 0) { o[i*3+0] = cx; o[i*3+1] = cy; o[i*3+2] = cz; }

        float bestv = -1.0f; unsigned besti = 0u;
#pragma unroll
        for (int k = 0; k < 4; k++) {
            int p = t + k*1024;
            float dx = sx[p]-cx, dy = sy[p]-cy, dz = sz[p]-cz;
            float d = __fadd_rn(__fadd_rn(__fmul_rn(dx,dx), __fmul_rn(dy,dy)),
                                __fmul_rn(dz,dz));
            float nd = fminf(dist[k], d);
            dist[k] = nd;
            if (nd > bestv) { bestv = nd; besti = (unsigned)p; }
        }
        // dist >= 0 -> float bits are uint-monotone
        unsigned uv = __float_as_uint(bestv);
        unsigned mv = __reduce_max_sync(0xffffffffu, uv);
        unsigned ci = (uv == mv) ? besti : 0xffffffffu;
        unsigned mi = __reduce_min_sync(0xffffffffu, ci);
        if (lane == 0) { wv[warp] = __uint_as_float(mv); wi[warp] = mi; }
        __syncthreads();
        if (warp == 0) {
            unsigned uv2 = __float_as_uint(wv[lane]);
            unsigned mv2 = __reduce_max_sync(0xffffffffu, uv2);
            unsigned ci2 = (uv2 == mv2) ? wi[lane] : 0xffffffffu;
            unsigned mi2 = __reduce_min_sync(0xffffffffu, ci2);
            if (lane == 0) sfar = (int)mi2;
        }
        __syncthreads();
        far_ = sfar;
    }
}

// =====================================================================
// 2) Ball query: one warp per (b,s). First 32 ascending indices with d<=r^2,
//    padded with the first found index. Early exit.
// =====================================================================
__global__ __launch_bounds__(128)
void ballquery_kernel(const float* __restrict__ xyz, const float* __restrict__ newxyz)
{
    const int w    = (blockIdx.x * 128 + threadIdx.x) >> 5;
    const int lane = threadIdx.x & 31;
    const int b = w >> 10, s = w & 1023;

    const float* nx = newxyz + ((size_t)(b*SPOINT + s))*3;
    const float cx = nx[0], cy = nx[1], cz = nx[2];
    const float r2 = 0.04f;
    const float* base = xyz + (size_t)b*NPTS*3;
    int* dst = g_ballidx + (size_t)w*KSAMP;

    int cnt = 0, first = 0;
    for (int b0 = 0; b0 < NPTS; b0 += 32) {
        int p = b0 + lane;
        float dx = nx ? (cx - base[p*3+0]) : 0.f;
        float dy = cy - base[p*3+1];
        float dz = cz - base[p*3+2];
        float d = __fadd_rn(__fadd_rn(__fmul_rn(dx,dx), __fmul_rn(dy,dy)),
                            __fmul_rn(dz,dz));
        bool in = !(d > r2);
        unsigned mask = __ballot_sync(0xffffffffu, in);
        if (cnt == 0 && mask) first = b0 + __ffs(mask) - 1;
        int pos = cnt + __popc(mask & ((1u << lane) - 1u));
        if (in && pos < KSAMP) dst[pos] = p;
        cnt += __popc(mask);
        if (cnt >= KSAMP) break;
    }
    if (cnt < KSAMP && lane < KSAMP - cnt) dst[cnt + lane] = first;
}

// =====================================================================
// GEMM: 128x64 tile, 128 threads, 8x8 register blocking.
// As: k-major [K][132] in dyn smem; Bs: [K][64]. Deterministic per-block
// channel stats. After the k-loop, smem is reused for stat reduction.
// =====================================================================

// ---- layer 0: gather prologue (xyz,points,ballidx), K=67 ----
__global__ __launch_bounds__(128, 4)
void gemm0_kernel(const float* __restrict__ xyz, const float* __restrict__ points,
                  const float* __restrict__ w0, const float* __restrict__ b0,
                  const float* __restrict__ newxyz)
{
    extern __shared__ float sm[];
    float* As = sm;                 // [67][132]
    float* Bs = sm + CIN*132;       // [67][64]

    const int tid  = threadIdx.x;
    const int row0 = blockIdx.x * 128;

    for (int i = tid; i < CIN*64; i += 128) {
        int k = i >> 6, oo = i & 63;
        Bs[k*64 + oo] = w0[oo*CIN + k];
    }
#pragma unroll
    for (int rr = 0; rr < 2; rr++) {
        int r = (tid >> 1) + rr*64;
        int half = tid & 1;
        int row = row0 + r;
        int bb = row >> 15;
        int ss = (row >> 5) & 1023;
        int idx = g_ballidx[row];
        const float* prow = points + ((size_t)(bb*NPTS + idx))*CFEAT;
#pragma unroll
        for (int j = 0; j < 8; j++) {
            int c = half*32 + j*4;
            float4 v = *(const float4*)(prow + c);
            As[(3+c+0)*132 + r] = v.x;
            As[(3+c+1)*132 + r] = v.y;
            As[(3+c+2)*132 + r] = v.z;
            As[(3+c+3)*132 + r] = v.w;
        }
        if (half == 0) {
            const float* pxyz = xyz + ((size_t)(bb*NPTS + idx))*3;
            const float* nx = newxyz + ((size_t)(bb*SPOINT + ss))*3;
            As[0*132 + r] = (pxyz[0]-nx[0]) / 0.2f;
            As[1*132 + r] = (pxyz[1]-nx[1]) / 0.2f;
            As[2*132 + r] = (pxyz[2]-nx[2]) / 0.2f;
        }
    }
    __syncthreads();

    const int cx = tid & 7, ry = tid >> 3;
    float acc[8][8];
#pragma unroll
    for (int i=0;i<8;i++)
#pragma unroll
        for (int j=0;j<8;j++) acc[i][j]=0.f;

#pragma unroll 4
    for (int k = 0; k < CIN; k++) {
        float4 a0 = *(const float4*)&As[k*132 + ry*8];
        float4 a1 = *(const float4*)&As[k*132 + ry*8 + 4];
        float4 c0 = *(const float4*)&Bs[k*64 + cx*8];
        float4 c1 = *(const float4*)&Bs[k*64 + cx*8 + 4];
        float av[8] = {a0.x,a0.y,a0.z,a0.w,a1.x,a1.y,a1.z,a1.w};
        float bv[8] = {c0.x,c0.y,c0.z,c0.w,c1.x,c1.y,c1.z,c1.w};
#pragma unroll
        for (int i=0;i<8;i++)
#pragma unroll
            for (int j=0;j<8;j++) acc[i][j] = fmaf(av[i], bv[j], acc[i][j]);
    }

    float bias[8], s8[8], q8[8];
#pragma unroll
    for (int j=0;j<8;j++){ bias[j]=b0[cx*8+j]; s8[j]=0.f; q8[j]=0.f; }
#pragma unroll
    for (int i=0;i<8;i++){
        float v[8];
#pragma unroll
        for (int j=0;j<8;j++){ v[j]=acc[i][j]+bias[j]; s8[j]+=v[j]; q8[j]=fmaf(v[j],v[j],q8[j]); }
        size_t row = (size_t)(row0 + ry*8 + i);
        *(float4*)&g_h0[row*64 + cx*8]     = make_float4(v[0],v[1],v[2],v[3]);
        *(float4*)&g_h0[row*64 + cx*8 + 4] = make_float4(v[4],v[5],v[6],v[7]);
    }
    const int lane = tid & 31, warp = tid >> 5;
#pragma unroll
    for (int j=0;j<8;j++){
        s8[j] += __shfl_xor_sync(0xffffffffu, s8[j], 8);
        s8[j] += __shfl_xor_sync(0xffffffffu, s8[j], 16);
        q8[j] += __shfl_xor_sync(0xffffffffu, q8[j], 8);
        q8[j] += __shfl_xor_sync(0xffffffffu, q8[j], 16);
    }
    __syncthreads();                       // smem reuse barrier
    float* sred  = sm;                     // [4][64]
    float* sqred = sm + 256;               // [4][64]
    if (lane < 8) {
#pragma unroll
        for (int j=0;j<8;j++){
            sred [warp*64 + lane*8 + j] = s8[j];
            sqred[warp*64 + lane*8 + j] = q8[j];
        }
    }
    __syncthreads();
    if (tid < 64) {
        g_psum[blockIdx.x*64 + tid] = sred [tid] + sred [64+tid] + sred [128+tid] + sred [192+tid];
        g_psq [blockIdx.x*64 + tid] = sqred[tid] + sqred[64+tid] + sqred[128+tid] + sqred[192+tid];
    }
}

// ---- layer 1: relu(affine(h0)) prologue, K=64, N=64 ----
__global__ __launch_bounds__(128, 4)
void gemm1_kernel(const float* __restrict__ w, const float* __restrict__ bb)
{
    extern __shared__ float sm[];
    float* As = sm;                 // [64][132]
    float* Bs = sm + 64*132;        // [64][64]

    const int tid  = threadIdx.x;
    const int row0 = blockIdx.x * 128;

    for (int i = tid; i < 64*64; i += 128) {
        int k = i >> 6, oo = i & 63;
        Bs[k*64 + oo] = w[oo*64 + k];
    }
    {
        const int c4 = (tid & 15) * 4, rb = tid >> 4;
        float4 a4 = *(const float4*)&g_scale[0][c4];
        float4 s4 = *(const float4*)&g_shift[0][c4];
#pragma unroll 4
        for (int rr = 0; rr < 16; rr++) {
            int r = rb + rr*8;
            float4 v = *(const float4*)&g_h0[(size_t)(row0+r)*64 + c4];
            As[(c4+0)*132 + r] = fmaxf(0.f, fmaf(a4.x, v.x, s4.x));
            As[(c4+1)*132 + r] = fmaxf(0.f, fmaf(a4.y, v.y, s4.y));
            As[(c4+2)*132 + r] = fmaxf(0.f, fmaf(a4.z, v.z, s4.z));
            As[(c4+3)*132 + r] = fmaxf(0.f, fmaf(a4.w, v.w, s4.w));
        }
    }
    __syncthreads();

    const int cx = tid & 7, ry = tid >> 3;
    float acc[8][8];
#pragma unroll
    for (int i=0;i<8;i++)
#pragma unroll
        for (int j=0;j<8;j++) acc[i][j]=0.f;

#pragma unroll 4
    for (int k = 0; k < 64; k++) {
        float4 a0 = *(const float4*)&As[k*132 + ry*8];
        float4 a1 = *(const float4*)&As[k*132 + ry*8 + 4];
        float4 c0 = *(const float4*)&Bs[k*64 + cx*8];
        float4 c1 = *(const float4*)&Bs[k*64 + cx*8 + 4];
        float av[8] = {a0.x,a0.y,a0.z,a0.w,a1.x,a1.y,a1.z,a1.w};
        float bv[8] = {c0.x,c0.y,c0.z,c0.w,c1.x,c1.y,c1.z,c1.w};
#pragma unroll
        for (int i=0;i<8;i++)
#pragma unroll
            for (int j=0;j<8;j++) acc[i][j] = fmaf(av[i], bv[j], acc[i][j]);
    }

    float bias[8], s8[8], q8[8];
#pragma unroll
    for (int j=0;j<8;j++){ bias[j]=bb[cx*8+j]; s8[j]=0.f; q8[j]=0.f; }
#pragma unroll
    for (int i=0;i<8;i++){
        float v[8];
#pragma unroll
        for (int j=0;j<8;j++){ v[j]=acc[i][j]+bias[j]; s8[j]+=v[j]; q8[j]=fmaf(v[j],v[j],q8[j]); }
        size_t row = (size_t)(row0 + ry*8 + i);
        *(float4*)&g_h1[row*64 + cx*8]     = make_float4(v[0],v[1],v[2],v[3]);
        *(float4*)&g_h1[row*64 + cx*8 + 4] = make_float4(v[4],v[5],v[6],v[7]);
    }
    const int lane = tid & 31, warp = tid >> 5;
#pragma unroll
    for (int j=0;j<8;j++){
        s8[j] += __shfl_xor_sync(0xffffffffu, s8[j], 8);
        s8[j] += __shfl_xor_sync(0xffffffffu, s8[j], 16);
        q8[j] += __shfl_xor_sync(0xffffffffu, q8[j], 8);
        q8[j] += __shfl_xor_sync(0xffffffffu, q8[j], 16);
    }
    __syncthreads();
    float* sred  = sm;
    float* sqred = sm + 256;
    if (lane < 8) {
#pragma unroll
        for (int j=0;j<8;j++){
            sred [warp*64 + lane*8 + j] = s8[j];
            sqred[warp*64 + lane*8 + j] = q8[j];
        }
    }
    __syncthreads();
    if (tid < 64) {
        g_psum[blockIdx.x*64 + tid] = sred [tid] + sred [64+tid] + sred [128+tid] + sred [192+tid];
        g_psq [blockIdx.x*64 + tid] = sqred[tid] + sqred[64+tid] + sqred[128+tid] + sqred[192+tid];
    }
}

// ---- layer 2: relu(affine(h1)) prologue, K=64, N=128 (2 col blocks).
//      Epilogue: per-group max/min (32 rows = 1 warp's tile rows) + stats.
__global__ __launch_bounds__(128, 4)
void gemm2_kernel(const float* __restrict__ w, const float* __restrict__ bb)
{
    extern __shared__ float sm[];
    float* As = sm;                 // [64][132]
    float* Bs = sm + 64*132;        // [64][64]

    const int tid   = threadIdx.x;
    const int row0  = blockIdx.x * 128;
    const int cblk  = blockIdx.y;          // 0 or 1 -> output channels cblk*64..+63

    for (int i = tid; i < 64*64; i += 128) {
        int k = i >> 6, oo = i & 63;
        Bs[k*64 + oo] = w[(cblk*64 + oo)*64 + k];
    }
    {
        const int c4 = (tid & 15) * 4, rb = tid >> 4;
        float4 a4 = *(const float4*)&g_scale[1][c4];
        float4 s4 = *(const float4*)&g_shift[1][c4];
#pragma unroll 4
        for (int rr = 0; rr < 16; rr++) {
            int r = rb + rr*8;
            float4 v = *(const float4*)&g_h1[(size_t)(row0+r)*64 + c4];
            As[(c4+0)*132 + r] = fmaxf(0.f, fmaf(a4.x, v.x, s4.x));
            As[(c4+1)*132 + r] = fmaxf(0.f, fmaf(a4.y, v.y, s4.y));
            As[(c4+2)*132 + r] = fmaxf(0.f, fmaf(a4.z, v.z, s4.z));
            As[(c4+3)*132 + r] = fmaxf(0.f, fmaf(a4.w, v.w, s4.w));
        }
    }
    __syncthreads();

    const int cx = tid & 7, ry = tid >> 3;
    float acc[8][8];
#pragma unroll
    for (int i=0;i<8;i++)
#pragma unroll
        for (int j=0;j<8;j++) acc[i][j]=0.f;

#pragma unroll 4
    for (int k = 0; k < 64; k++) {
        float4 a0 = *(const float4*)&As[k*132 + ry*8];
        float4 a1 = *(const float4*)&As[k*132 + ry*8 + 4];
        float4 c0 = *(const float4*)&Bs[k*64 + cx*8];
        float4 c1 = *(const float4*)&Bs[k*64 + cx*8 + 4];
        float av[8] = {a0.x,a0.y,a0.z,a0.w,a1.x,a1.y,a1.z,a1.w};
        float bv[8] = {c0.x,c0.y,c0.z,c0.w,c1.x,c1.y,c1.z,c1.w};
#pragma unroll
        for (int i=0;i<8;i++)
#pragma unroll
            for (int j=0;j<8;j++) acc[i][j] = fmaf(av[i], bv[j], acc[i][j]);
    }

    float bias[8], s8[8], q8[8], mx[8], mn[8];
#pragma unroll
    for (int j=0;j<8;j++){
        bias[j]=bb[cblk*64 + cx*8 + j]; s8[j]=0.f; q8[j]=0.f;
        mx[j]=-3.4e38f; mn[j]=3.4e38f;
    }
#pragma unroll
    for (int i=0;i<8;i++){
#pragma unroll
        for (int j=0;j<8;j++){
            float v = acc[i][j]+bias[j];
            s8[j]+=v; q8[j]=fmaf(v,v,q8[j]);
            mx[j]=fmaxf(mx[j],v); mn[j]=fminf(mn[j],v);
        }
    }
    const int lane = tid & 31, warp = tid >> 5;
#pragma unroll
    for (int j=0;j<8;j++){
        s8[j] += __shfl_xor_sync(0xffffffffu, s8[j], 8);
        s8[j] += __shfl_xor_sync(0xffffffffu, s8[j], 16);
        q8[j] += __shfl_xor_sync(0xffffffffu, q8[j], 8);
        q8[j] += __shfl_xor_sync(0xffffffffu, q8[j], 16);
        mx[j] = fmaxf(mx[j], __shfl_xor_sync(0xffffffffu, mx[j], 8));
        mx[j] = fmaxf(mx[j], __shfl_xor_sync(0xffffffffu, mx[j], 16));
        mn[j] = fminf(mn[j], __shfl_xor_sync(0xffffffffu, mn[j], 8));
        mn[j] = fminf(mn[j], __shfl_xor_sync(0xffffffffu, mn[j], 16));
    }
    // warp w covers rows w*32..w*32+31 of the tile = group blockIdx.x*4 + w
    if (lane < 8) {
        size_t grp = (size_t)blockIdx.x*4 + warp;
#pragma unroll
        for (int j=0;j<8;j++){
            g_gmax[grp*128 + cblk*64 + lane*8 + j] = mx[j];
            g_gmin[grp*128 + cblk*64 + lane*8 + j] = mn[j];
        }
    }
    __syncthreads();
    float* sred  = sm;
    float* sqred = sm + 256;
    if (lane < 8) {
#pragma unroll
        for (int j=0;j<8;j++){
            sred [warp*64 + lane*8 + j] = s8[j];
            sqred[warp*64 + lane*8 + j] = q8[j];
        }
    }
    __syncthreads();
    if (tid < 64) {
        g_psum[blockIdx.x*128 + cblk*64 + tid] = sred [tid] + sred [64+tid] + sred [128+tid] + sred [192+tid];
        g_psq [blockIdx.x*128 + cblk*64 + tid] = sqred[tid] + sqred[64+tid] + sqred[128+tid] + sqred[192+tid];
    }
}

// =====================================================================
// Stats fold: BN -> per-channel affine (a, c). Deterministic fixed-order sum.
// =====================================================================
__global__ void stats_kernel(const float* __restrict__ g, const float* __restrict__ be,
                             int layer, int nch)
{
    int ch = threadIdx.x;
    if (ch >= nch) return;
    double s = 0.0, q = 0.0;
    for (int b = 0; b < NBLK; b++) {
        s += (double)g_psum[b*nch + ch];
        q += (double)g_psq [b*nch + ch];
    }
    const double M = (double)MROWS;
    double mu  = s / M;
    double var = q / M - mu*mu;
    float rs = (float)(1.0 / sqrt(var + 1e-5));
    float a  = g[ch] * rs;
    float c  = be[ch] - (float)mu * a;
    g_scale[layer][ch] = a;
    g_shift[layer][ch] = c;
}

// =====================================================================
// Final: new_points[grp][ch] = relu(a * (a>=0 ? gmax : gmin) + c)
// =====================================================================
__global__ void final_kernel(float* __restrict__ out)
{
    int grp = blockIdx.x, ch = threadIdx.x;
    float a = g_scale[2][ch], c = g_shift[2][ch];
    float h = (a >= 0.f) ? g_gmax[(size_t)grp*128 + ch] : g_gmin[(size_t)grp*128 + ch];
    out[OUT_XYZ_ELEMS + (size_t)grp*128 + ch] = fmaxf(0.f, fmaf(a, h, c));
}

// =====================================================================
extern "C" void kernel_launch(void* const* d_in, const int* in_sizes, int n_in,
                              void* d_out, int out_size)
{
    const float* xyz    = (const float*)d_in[0];
    const float* points = (const float*)d_in[1];
    const float* w0  = (const float*)d_in[2];
    const float* b0  = (const float*)d_in[3];
    const float* g0  = (const float*)d_in[4];
    const float* be0 = (const float*)d_in[5];
    const float* w1  = (const float*)d_in[6];
    const float* b1  = (const float*)d_in[7];
    const float* g1  = (const float*)d_in[8];
    const float* be1 = (const float*)d_in[9];
    const float* w2  = (const float*)d_in[10];
    const float* b2  = (const float*)d_in[11];
    const float* g2  = (const float*)d_in[12];
    const float* be2 = (const float*)d_in[13];
    float* out = (float*)d_out;

    const int FPS_SM   = NPTS*3*4;           // 49152
    const int GEMM0_SM = CIN*(132+64)*4;     // 52528
    const int GEMM_SM  = 64*(132+64)*4;      // 50176
    cudaFuncSetAttribute(fps_kernel,   cudaFuncAttributeMaxDynamicSharedMemorySize, FPS_SM);
    cudaFuncSetAttribute(gemm0_kernel, cudaFuncAttributeMaxDynamicSharedMemorySize, GEMM0_SM);
    cudaFuncSetAttribute(gemm1_kernel, cudaFuncAttributeMaxDynamicSharedMemorySize, GEMM_SM);
    cudaFuncSetAttribute(gemm2_kernel, cudaFuncAttributeMaxDynamicSharedMemorySize, GEMM_SM);

    fps_kernel<<<BATCH, 1024, FPS_SM>>>(xyz, out);
    ballquery_kernel<<<(NGROUP*32)/128, 128>>>(xyz, out);
    gemm0_kernel<<<NBLK, 128, GEMM0_SM>>>(xyz, points, w0, b0, out);
    stats_kernel<<<1, 128>>>(g0, be0, 0, 64);
    gemm1_kernel<<<NBLK, 128, GEMM_SM>>>(w1, b1);
    stats_kernel<<<1, 128>>>(g1, be1, 1, 64);
    dim3 g2grid(NBLK, 2);
    gemm2_kernel<<<g2grid, 128, GEMM_SM>>>(w2, b2);
    stats_kernel<<<1, 128>>>(g2, be2, 2, 128);
    final_kernel<<<NGROUP, 128>>>(out);
}

// round 3
// speedup vs baseline: 1.6314x; 1.6314x over previous
#include <cuda_runtime.h>
#include <cuda_bf16.h>
#include <cstdint>
#include <math.h>

// ---------------- problem constants ----------------
#define BATCH    16
#define NPTS     4096
#define CFEAT    64
#define SPOINT   1024
#define KSAMP    32
#define CIN      67
#define MROWS    (BATCH*SPOINT*KSAMP)      // 524288
#define NGROUP   (BATCH*SPOINT)            // 16384
#define NBLK     (MROWS/128)               // 4096
#define OUT_XYZ_ELEMS (BATCH*SPOINT*3)     // 49152

// ---------------- device scratch (no allocs allowed) ----------------
__device__ int   g_ballidx[MROWS];
__device__ float g_h0[(size_t)MROWS*64];
__device__ float g_h1[(size_t)MROWS*64];
__device__ float g_gmax[(size_t)NGROUP*128];
__device__ float g_gmin[(size_t)NGROUP*128];
__device__ float g_psum[NBLK*128];
__device__ float g_psq [NBLK*128];
__device__ float g_scale[3][128];
__device__ float g_shift[3][128];

// =====================================================================
// 1) FPS. One block/batch, 1024 threads, 4 pts/thread IN REGISTERS.
//    One __syncthreads per step via double-buffered warp-maxima; every
//    warp redundantly reduces the 32 warp results (same answer everywhere).
//    Exact lowest-index tie-break argmax (matches jnp.argmax).
// =====================================================================
__global__ void fps_kernel(const float* __restrict__ xyz, float* __restrict__ out_xyz)
{
    extern __shared__ float sh[];            // sx[4096] sy[4096] sz[4096]
    float* sx = sh;
    float* sy = sh + NPTS;
    float* sz = sh + 2*NPTS;
    __shared__ float    wv[2][32];
    __shared__ unsigned wi[2][32];

    const int b = blockIdx.x, t = threadIdx.x;
    const int lane = t & 31, warp = t >> 5;
    const float* base = xyz + (size_t)b*NPTS*3;

    float px[4], py[4], pz[4], dist[4];
#pragma unroll
    for (int k = 0; k < 4; k++) {
        int p = t + k*1024;
        float x = base[p*3+0], y = base[p*3+1], z = base[p*3+2];
        px[k]=x; py[k]=y; pz[k]=z;
        sx[p]=x; sy[p]=y; sz[p]=z;
        dist[k] = 1e10f;
    }
    __syncthreads();

    int far_ = 0;
    float* o = out_xyz + (size_t)b*SPOINT*3;

    for (int i = 0; i < SPOINT; i++) {
        const int buf = i & 1;
        float cx = sx[far_], cy = sy[far_], cz = sz[far_];
        if (t == 0) { o[i*3+0] = cx; o[i*3+1] = cy; o[i*3+2] = cz; }

        float bestv = -1.0f; unsigned besti = 0u;
#pragma unroll
        for (int k = 0; k < 4; k++) {
            float dx = px[k]-cx, dy = py[k]-cy, dz = pz[k]-cz;
            float d = __fadd_rn(__fadd_rn(__fmul_rn(dx,dx), __fmul_rn(dy,dy)),
                                __fmul_rn(dz,dz));
            float nd = fminf(dist[k], d);
            dist[k] = nd;
            if (nd > bestv) { bestv = nd; besti = (unsigned)(t + k*1024); }
        }
        // dist >= 0 -> float bits are uint-monotone
        unsigned uv = __float_as_uint(bestv);
        unsigned mv = __reduce_max_sync(0xffffffffu, uv);
        unsigned ci = (uv == mv) ? besti : 0xffffffffu;
        unsigned mi = __reduce_min_sync(0xffffffffu, ci);
        if (lane == 0) { wv[buf][warp] = __uint_as_float(mv); wi[buf][warp] = mi; }
        __syncthreads();
        // every warp reduces the 32 warp-maxima (identical deterministic result)
        unsigned uv2 = __float_as_uint(wv[buf][lane]);
        unsigned mv2 = __reduce_max_sync(0xffffffffu, uv2);
        unsigned ci2 = (uv2 == mv2) ? wi[buf][lane] : 0xffffffffu;
        far_ = (int)__reduce_min_sync(0xffffffffu, ci2);
        // no second barrier: next step writes the other buffer
    }
}

// =====================================================================
// 2) Ball query: one warp per (b,s). First 32 ascending indices with d<=r^2,
//    padded with the first found index. Early exit.
// =====================================================================
__global__ __launch_bounds__(128)
void ballquery_kernel(const float* __restrict__ xyz, const float* __restrict__ newxyz)
{
    const int w    = (blockIdx.x * 128 + threadIdx.x) >> 5;
    const int lane = threadIdx.x & 31;
    const int b = w >> 10, s = w & 1023;

    const float* nx = newxyz + ((size_t)(b*SPOINT + s))*3;
    const float cx = nx[0], cy = nx[1], cz = nx[2];
    const float r2 = 0.04f;
    const float* base = xyz + (size_t)b*NPTS*3;
    int* dst = g_ballidx + (size_t)w*KSAMP;

    int cnt = 0, first = 0;
    for (int b0 = 0; b0 < NPTS; b0 += 32) {
        int p = b0 + lane;
        float dx = cx - base[p*3+0];
        float dy = cy - base[p*3+1];
        float dz = cz - base[p*3+2];
        float d = __fadd_rn(__fadd_rn(__fmul_rn(dx,dx), __fmul_rn(dy,dy)),
                            __fmul_rn(dz,dz));
        bool in = !(d > r2);
        unsigned mask = __ballot_sync(0xffffffffu, in);
        if (cnt == 0 && mask) first = b0 + __ffs(mask) - 1;
        int pos = cnt + __popc(mask & ((1u << lane) - 1u));
        if (in && pos < KSAMP) dst[pos] = p;
        cnt += __popc(mask);
        if (cnt >= KSAMP) break;
    }
    if (cnt < KSAMP && lane < KSAMP - cnt) dst[cnt + lane] = first;
}

// =====================================================================
// GEMM: 128x64 tile, 128 threads, 8x8 register blocking. NO occupancy
// floor -> no register spills (acc 64 regs + unroll staging ~ 170 regs).
// =====================================================================

// ---- layer 0: gather prologue (xyz,points,ballidx), K=67 ----
__global__ __launch_bounds__(128)
void gemm0_kernel(const float* __restrict__ xyz, const float* __restrict__ points,
                  const float* __restrict__ w0, const float* __restrict__ b0,
                  const float* __restrict__ newxyz)
{
    extern __shared__ float sm[];
    float* As = sm;                 // [67][132]
    float* Bs = sm + CIN*132;       // [67][64]

    const int tid  = threadIdx.x;
    const int row0 = blockIdx.x * 128;

    for (int i = tid; i < CIN*64; i += 128) {
        int k = i >> 6, oo = i & 63;
        Bs[k*64 + oo] = w0[oo*CIN + k];
    }
#pragma unroll
    for (int rr = 0; rr < 2; rr++) {
        int r = (tid >> 1) + rr*64;
        int half = tid & 1;
        int row = row0 + r;
        int bb = row >> 15;
        int ss = (row >> 5) & 1023;
        int idx = g_ballidx[row];
        const float* prow = points + ((size_t)(bb*NPTS + idx))*CFEAT;
#pragma unroll
        for (int j = 0; j < 8; j++) {
            int c = half*32 + j*4;
            float4 v = *(const float4*)(prow + c);
            As[(3+c+0)*132 + r] = v.x;
            As[(3+c+1)*132 + r] = v.y;
            As[(3+c+2)*132 + r] = v.z;
            As[(3+c+3)*132 + r] = v.w;
        }
        if (half == 0) {
            const float* pxyz = xyz + ((size_t)(bb*NPTS + idx))*3;
            const float* nx = newxyz + ((size_t)(bb*SPOINT + ss))*3;
            As[0*132 + r] = (pxyz[0]-nx[0]) / 0.2f;
            As[1*132 + r] = (pxyz[1]-nx[1]) / 0.2f;
            As[2*132 + r] = (pxyz[2]-nx[2]) / 0.2f;
        }
    }
    __syncthreads();

    const int cx = tid & 7, ry = tid >> 3;
    float acc[8][8];
#pragma unroll
    for (int i=0;i<8;i++)
#pragma unroll
        for (int j=0;j<8;j++) acc[i][j]=0.f;

#pragma unroll 4
    for (int k = 0; k < CIN; k++) {
        float4 a0 = *(const float4*)&As[k*132 + ry*8];
        float4 a1 = *(const float4*)&As[k*132 + ry*8 + 4];
        float4 c0 = *(const float4*)&Bs[k*64 + cx*8];
        float4 c1 = *(const float4*)&Bs[k*64 + cx*8 + 4];
        float av[8] = {a0.x,a0.y,a0.z,a0.w,a1.x,a1.y,a1.z,a1.w};
        float bv[8] = {c0.x,c0.y,c0.z,c0.w,c1.x,c1.y,c1.z,c1.w};
#pragma unroll
        for (int i=0;i<8;i++)
#pragma unroll
            for (int j=0;j<8;j++) acc[i][j] = fmaf(av[i], bv[j], acc[i][j]);
    }

    float bias[8], s8[8], q8[8];
#pragma unroll
    for (int j=0;j<8;j++){ bias[j]=b0[cx*8+j]; s8[j]=0.f; q8[j]=0.f; }
#pragma unroll
    for (int i=0;i<8;i++){
        float v[8];
#pragma unroll
        for (int j=0;j<8;j++){ v[j]=acc[i][j]+bias[j]; s8[j]+=v[j]; q8[j]=fmaf(v[j],v[j],q8[j]); }
        size_t row = (size_t)(row0 + ry*8 + i);
        *(float4*)&g_h0[row*64 + cx*8]     = make_float4(v[0],v[1],v[2],v[3]);
        *(float4*)&g_h0[row*64 + cx*8 + 4] = make_float4(v[4],v[5],v[6],v[7]);
    }
    const int lane = tid & 31, warp = tid >> 5;
#pragma unroll
    for (int j=0;j<8;j++){
        s8[j] += __shfl_xor_sync(0xffffffffu, s8[j], 8);
        s8[j] += __shfl_xor_sync(0xffffffffu, s8[j], 16);
        q8[j] += __shfl_xor_sync(0xffffffffu, q8[j], 8);
        q8[j] += __shfl_xor_sync(0xffffffffu, q8[j], 16);
    }
    __syncthreads();                       // smem reuse barrier
    float* sred  = sm;                     // [4][64]
    float* sqred = sm + 256;               // [4][64]
    if (lane < 8) {
#pragma unroll
        for (int j=0;j<8;j++){
            sred [warp*64 + lane*8 + j] = s8[j];
            sqred[warp*64 + lane*8 + j] = q8[j];
        }
    }
    __syncthreads();
    if (tid < 64) {
        g_psum[blockIdx.x*64 + tid] = sred [tid] + sred [64+tid] + sred [128+tid] + sred [192+tid];
        g_psq [blockIdx.x*64 + tid] = sqred[tid] + sqred[64+tid] + sqred[128+tid] + sqred[192+tid];
    }
}

// ---- layer 1: relu(affine(h0)) prologue, K=64, N=64 ----
__global__ __launch_bounds__(128)
void gemm1_kernel(const float* __restrict__ w, const float* __restrict__ bb)
{
    extern __shared__ float sm[];
    float* As = sm;                 // [64][132]
    float* Bs = sm + 64*132;        // [64][64]

    const int tid  = threadIdx.x;
    const int row0 = blockIdx.x * 128;

    for (int i = tid; i < 64*64; i += 128) {
        int k = i >> 6, oo = i & 63;
        Bs[k*64 + oo] = w[oo*64 + k];
    }
    {
        const int c4 = (tid & 15) * 4, rb = tid >> 4;
        float4 a4 = *(const float4*)&g_scale[0][c4];
        float4 s4 = *(const float4*)&g_shift[0][c4];
#pragma unroll 4
        for (int rr = 0; rr < 16; rr++) {
            int r = rb + rr*8;
            float4 v = *(const float4*)&g_h0[(size_t)(row0+r)*64 + c4];
            As[(c4+0)*132 + r] = fmaxf(0.f, fmaf(a4.x, v.x, s4.x));
            As[(c4+1)*132 + r] = fmaxf(0.f, fmaf(a4.y, v.y, s4.y));
            As[(c4+2)*132 + r] = fmaxf(0.f, fmaf(a4.z, v.z, s4.z));
            As[(c4+3)*132 + r] = fmaxf(0.f, fmaf(a4.w, v.w, s4.w));
        }
    }
    __syncthreads();

    const int cx = tid & 7, ry = tid >> 3;
    float acc[8][8];
#pragma unroll
    for (int i=0;i<8;i++)
#pragma unroll
        for (int j=0;j<8;j++) acc[i][j]=0.f;

#pragma unroll 4
    for (int k = 0; k < 64; k++) {
        float4 a0 = *(const float4*)&As[k*132 + ry*8];
        float4 a1 = *(const float4*)&As[k*132 + ry*8 + 4];
        float4 c0 = *(const float4*)&Bs[k*64 + cx*8];
        float4 c1 = *(const float4*)&Bs[k*64 + cx*8 + 4];
        float av[8] = {a0.x,a0.y,a0.z,a0.w,a1.x,a1.y,a1.z,a1.w};
        float bv[8] = {c0.x,c0.y,c0.z,c0.w,c1.x,c1.y,c1.z,c1.w};
#pragma unroll
        for (int i=0;i<8;i++)
#pragma unroll
            for (int j=0;j<8;j++) acc[i][j] = fmaf(av[i], bv[j], acc[i][j]);
    }

    float bias[8], s8[8], q8[8];
#pragma unroll
    for (int j=0;j<8;j++){ bias[j]=bb[cx*8+j]; s8[j]=0.f; q8[j]=0.f; }
#pragma unroll
    for (int i=0;i<8;i++){
        float v[8];
#pragma unroll
        for (int j=0;j<8;j++){ v[j]=acc[i][j]+bias[j]; s8[j]+=v[j]; q8[j]=fmaf(v[j],v[j],q8[j]); }
        size_t row = (size_t)(row0 + ry*8 + i);
        *(float4*)&g_h1[row*64 + cx*8]     = make_float4(v[0],v[1],v[2],v[3]);
        *(float4*)&g_h1[row*64 + cx*8 + 4] = make_float4(v[4],v[5],v[6],v[7]);
    }
    const int lane = tid & 31, warp = tid >> 5;
#pragma unroll
    for (int j=0;j<8;j++){
        s8[j] += __shfl_xor_sync(0xffffffffu, s8[j], 8);
        s8[j] += __shfl_xor_sync(0xffffffffu, s8[j], 16);
        q8[j] += __shfl_xor_sync(0xffffffffu, q8[j], 8);
        q8[j] += __shfl_xor_sync(0xffffffffu, q8[j], 16);
    }
    __syncthreads();
    float* sred  = sm;
    float* sqred = sm + 256;
    if (lane < 8) {
#pragma unroll
        for (int j=0;j<8;j++){
            sred [warp*64 + lane*8 + j] = s8[j];
            sqred[warp*64 + lane*8 + j] = q8[j];
        }
    }
    __syncthreads();
    if (tid < 64) {
        g_psum[blockIdx.x*64 + tid] = sred [tid] + sred [64+tid] + sred [128+tid] + sred [192+tid];
        g_psq [blockIdx.x*64 + tid] = sqred[tid] + sqred[64+tid] + sqred[128+tid] + sqred[192+tid];
    }
}

// ---- layer 2: relu(affine(h1)) prologue, K=64, N=128 (2 col blocks).
//      Epilogue: per-group max/min (group = 32 consecutive rows) + stats.
__global__ __launch_bounds__(128)
void gemm2_kernel(const float* __restrict__ w, const float* __restrict__ bb)
{
    extern __shared__ float sm[];
    float* As = sm;                 // [64][132]
    float* Bs = sm + 64*132;        // [64][64]

    const int tid   = threadIdx.x;
    const int row0  = blockIdx.x * 128;
    const int cblk  = blockIdx.y;          // 0/1 -> channels cblk*64..+63

    for (int i = tid; i < 64*64; i += 128) {
        int k = i >> 6, oo = i & 63;
        Bs[k*64 + oo] = w[(cblk*64 + oo)*64 + k];
    }
    {
        const int c4 = (tid & 15) * 4, rb = tid >> 4;
        float4 a4 = *(const float4*)&g_scale[1][c4];
        float4 s4 = *(const float4*)&g_shift[1][c4];
#pragma unroll 4
        for (int rr = 0; rr < 16; rr++) {
            int r = rb + rr*8;
            float4 v = *(const float4*)&g_h1[(size_t)(row0+r)*64 + c4];
            As[(c4+0)*132 + r] = fmaxf(0.f, fmaf(a4.x, v.x, s4.x));
            As[(c4+1)*132 + r] = fmaxf(0.f, fmaf(a4.y, v.y, s4.y));
            As[(c4+2)*132 + r] = fmaxf(0.f, fmaf(a4.z, v.z, s4.z));
            As[(c4+3)*132 + r] = fmaxf(0.f, fmaf(a4.w, v.w, s4.w));
        }
    }
    __syncthreads();

    const int cx = tid & 7, ry = tid >> 3;
    float acc[8][8];
#pragma unroll
    for (int i=0;i<8;i++)
#pragma unroll
        for (int j=0;j<8;j++) acc[i][j]=0.f;

#pragma unroll 4
    for (int k = 0; k < 64; k++) {
        float4 a0 = *(const float4*)&As[k*132 + ry*8];
        float4 a1 = *(const float4*)&As[k*132 + ry*8 + 4];
        float4 c0 = *(const float4*)&Bs[k*64 + cx*8];
        float4 c1 = *(const float4*)&Bs[k*64 + cx*8 + 4];
        float av[8] = {a0.x,a0.y,a0.z,a0.w,a1.x,a1.y,a1.z,a1.w};
        float bv[8] = {c0.x,c0.y,c0.z,c0.w,c1.x,c1.y,c1.z,c1.w};
#pragma unroll
        for (int i=0;i<8;i++)
#pragma unroll
            for (int j=0;j<8;j++) acc[i][j] = fmaf(av[i], bv[j], acc[i][j]);
    }

    float bias[8], s8[8], q8[8], mx[8], mn[8];
#pragma unroll
    for (int j=0;j<8;j++){
        bias[j]=bb[cblk*64 + cx*8 + j]; s8[j]=0.f; q8[j]=0.f;
        mx[j]=-3.4e38f; mn[j]=3.4e38f;
    }
#pragma unroll
    for (int i=0;i<8;i++){
#pragma unroll
        for (int j=0;j<8;j++){
            float v = acc[i][j]+bias[j];
            s8[j]+=v; q8[j]=fmaf(v,v,q8[j]);
            mx[j]=fmaxf(mx[j],v); mn[j]=fminf(mn[j],v);
        }
    }
    const int lane = tid & 31, warp = tid >> 5;
#pragma unroll
    for (int j=0;j<8;j++){
        s8[j] += __shfl_xor_sync(0xffffffffu, s8[j], 8);
        s8[j] += __shfl_xor_sync(0xffffffffu, s8[j], 16);
        q8[j] += __shfl_xor_sync(0xffffffffu, q8[j], 8);
        q8[j] += __shfl_xor_sync(0xffffffffu, q8[j], 16);
        mx[j] = fmaxf(mx[j], __shfl_xor_sync(0xffffffffu, mx[j], 8));
        mx[j] = fmaxf(mx[j], __shfl_xor_sync(0xffffffffu, mx[j], 16));
        mn[j] = fminf(mn[j], __shfl_xor_sync(0xffffffffu, mn[j], 8));
        mn[j] = fminf(mn[j], __shfl_xor_sync(0xffffffffu, mn[j], 16));
    }
    if (lane < 8) {
        size_t grp = (size_t)blockIdx.x*4 + warp;
#pragma unroll
        for (int j=0;j<8;j++){
            g_gmax[grp*128 + cblk*64 + lane*8 + j] = mx[j];
            g_gmin[grp*128 + cblk*64 + lane*8 + j] = mn[j];
        }
    }
    __syncthreads();
    float* sred  = sm;
    float* sqred = sm + 256;
    if (lane < 8) {
#pragma unroll
        for (int j=0;j<8;j++){
            sred [warp*64 + lane*8 + j] = s8[j];
            sqred[warp*64 + lane*8 + j] = q8[j];
        }
    }
    __syncthreads();
    if (tid < 64) {
        g_psum[blockIdx.x*128 + cblk*64 + tid] = sred [tid] + sred [64+tid] + sred [128+tid] + sred [192+tid];
        g_psq [blockIdx.x*128 + cblk*64 + tid] = sqred[tid] + sqred[64+tid] + sqred[128+tid] + sqred[192+tid];
    }
}

// =====================================================================
// Stats fold: BN -> per-channel affine (a, c). Deterministic fixed-order sum.
// =====================================================================
__global__ void stats_kernel(const float* __restrict__ g, const float* __restrict__ be,
                             int layer, int nch)
{
    int ch = threadIdx.x;
    if (ch >= nch) return;
    double s = 0.0, q = 0.0;
    for (int b = 0; b < NBLK; b++) {
        s += (double)g_psum[b*nch + ch];
        q += (double)g_psq [b*nch + ch];
    }
    const double M = (double)MROWS;
    double mu  = s / M;
    double var = q / M - mu*mu;
    float rs = (float)(1.0 / sqrt(var + 1e-5));
    float a  = g[ch] * rs;
    float c  = be[ch] - (float)mu * a;
    g_scale[layer][ch] = a;
    g_shift[layer][ch] = c;
}

// =====================================================================
// Final: new_points[grp][ch] = relu(a * (a>=0 ? gmax : gmin) + c)
// =====================================================================
__global__ void final_kernel(float* __restrict__ out)
{
    int grp = blockIdx.x, ch = threadIdx.x;
    float a = g_scale[2][ch], c = g_shift[2][ch];
    float h = (a >= 0.f) ? g_gmax[(size_t)grp*128 + ch] : g_gmin[(size_t)grp*128 + ch];
    out[OUT_XYZ_ELEMS + (size_t)grp*128 + ch] = fmaxf(0.f, fmaf(a, h, c));
}

// =====================================================================
extern "C" void kernel_launch(void* const* d_in, const int* in_sizes, int n_in,
                              void* d_out, int out_size)
{
    const float* xyz    = (const float*)d_in[0];
    const float* points = (const float*)d_in[1];
    const float* w0  = (const float*)d_in[2];
    const float* b0  = (const float*)d_in[3];
    const float* g0  = (const float*)d_in[4];
    const float* be0 = (const float*)d_in[5];
    const float* w1  = (const float*)d_in[6];
    const float* b1  = (const float*)d_in[7];
    const float* g1  = (const float*)d_in[8];
    const float* be1 = (const float*)d_in[9];
    const float* w2  = (const float*)d_in[10];
    const float* b2  = (const float*)d_in[11];
    const float* g2  = (const float*)d_in[12];
    const float* be2 = (const float*)d_in[13];
    float* out = (float*)d_out;

    const int FPS_SM   = NPTS*3*4;           // 49152
    const int GEMM0_SM = CIN*(132+64)*4;     // 52528
    const int GEMM_SM  = 64*(132+64)*4;      // 50176
    cudaFuncSetAttribute(fps_kernel,   cudaFuncAttributeMaxDynamicSharedMemorySize, FPS_SM);
    cudaFuncSetAttribute(gemm0_kernel, cudaFuncAttributeMaxDynamicSharedMemorySize, GEMM0_SM);
    cudaFuncSetAttribute(gemm1_kernel, cudaFuncAttributeMaxDynamicSharedMemorySize, GEMM_SM);
    cudaFuncSetAttribute(gemm2_kernel, cudaFuncAttributeMaxDynamicSharedMemorySize, GEMM_SM);

    fps_kernel<<<BATCH, 1024, FPS_SM>>>(xyz, out);
    ballquery_kernel<<<(NGROUP*32)/128, 128>>>(xyz, out);
    gemm0_kernel<<<NBLK, 128, GEMM0_SM>>>(xyz, points, w0, b0, out);
    stats_kernel<<<1, 128>>>(g0, be0, 0, 64);
    gemm1_kernel<<<NBLK, 128, GEMM_SM>>>(w1, b1);
    stats_kernel<<<1, 128>>>(g1, be1, 1, 64);
    dim3 g2grid(NBLK, 2);
    gemm2_kernel<<<g2grid, 128, GEMM_SM>>>(w2, b2);
    stats_kernel<<<1, 128>>>(g2, be2, 2, 128);
    final_kernel<<<NGROUP, 128>>>(out);
}

// round 5
// speedup vs baseline: 4.0135x; 2.4602x over previous
#include <cuda_runtime.h>
#include <cuda_bf16.h>
#include <cstdint>
#include <math.h>

// ---------------- problem constants ----------------
#define BATCH    16
#define NPTS     4096
#define CFEAT    64
#define SPOINT   1024
#define KSAMP    32
#define CIN      67
#define MROWS    (BATCH*SPOINT*KSAMP)      // 524288
#define NGROUP   (BATCH*SPOINT)            // 16384
#define NBLK     (MROWS/128)               // 4096
#define OUT_XYZ_ELEMS (BATCH*SPOINT*3)     // 49152

// ---------------- device scratch (no allocs allowed) ----------------
__device__ int   g_ballidx[MROWS];
__device__ float g_h0[(size_t)MROWS*64];
__device__ float g_h1[(size_t)MROWS*64];
__device__ float g_gmax[(size_t)NGROUP*128];
__device__ float g_gmin[(size_t)NGROUP*128];
__device__ float g_psum[NBLK*128];
__device__ float g_psq [NBLK*128];
__device__ float g_scale[3][128];
__device__ float g_shift[3][128];

// =====================================================================
// 1) FPS. One block/batch, 1024 threads, 4 pts/thread IN REGISTERS.
//    One __syncthreads per step via double-buffered warp-maxima; every
//    warp redundantly reduces the 32 warp results (same answer everywhere).
//    Exact lowest-index tie-break argmax (matches jnp.argmax).
// =====================================================================
__global__ void fps_kernel(const float* __restrict__ xyz, float* __restrict__ out_xyz)
{
    extern __shared__ float sh[];            // sx[4096] sy[4096] sz[4096]
    float* sx = sh;
    float* sy = sh + NPTS;
    float* sz = sh + 2*NPTS;
    __shared__ float    wv[2][32];
    __shared__ unsigned wi[2][32];

    const int b = blockIdx.x, t = threadIdx.x;
    const int lane = t & 31, warp = t >> 5;
    const float* base = xyz + (size_t)b*NPTS*3;

    float px[4], py[4], pz[4], dist[4];
#pragma unroll
    for (int k = 0; k < 4; k++) {
        int p = t + k*1024;
        float x = base[p*3+0], y = base[p*3+1], z = base[p*3+2];
        px[k]=x; py[k]=y; pz[k]=z;
        sx[p]=x; sy[p]=y; sz[p]=z;
        dist[k] = 1e10f;
    }
    __syncthreads();

    int far_ = 0;
    float* o = out_xyz + (size_t)b*SPOINT*3;

    for (int i = 0; i < SPOINT; i++) {
        const int buf = i & 1;
        float cx = sx[far_], cy = sy[far_], cz = sz[far_];
        if (t == 0) { o[i*3+0] = cx; o[i*3+1] = cy; o[i*3+2] = cz; }

        float bestv = -1.0f; unsigned besti = 0u;
#pragma unroll
        for (int k = 0; k < 4; k++) {
            float dx = px[k]-cx, dy = py[k]-cy, dz = pz[k]-cz;
            float d = __fadd_rn(__fadd_rn(__fmul_rn(dx,dx), __fmul_rn(dy,dy)),
                                __fmul_rn(dz,dz));
            float nd = fminf(dist[k], d);
            dist[k] = nd;
            if (nd > bestv) { bestv = nd; besti = (unsigned)(t + k*1024); }
        }
        // dist >= 0 -> float bits are uint-monotone
        unsigned uv = __float_as_uint(bestv);
        unsigned mv = __reduce_max_sync(0xffffffffu, uv);
        unsigned ci = (uv == mv) ? besti : 0xffffffffu;
        unsigned mi = __reduce_min_sync(0xffffffffu, ci);
        if (lane == 0) { wv[buf][warp] = __uint_as_float(mv); wi[buf][warp] = mi; }
        __syncthreads();
        // every warp reduces the 32 warp-maxima (identical deterministic result)
        unsigned uv2 = __float_as_uint(wv[buf][lane]);
        unsigned mv2 = __reduce_max_sync(0xffffffffu, uv2);
        unsigned ci2 = (uv2 == mv2) ? wi[buf][lane] : 0xffffffffu;
        far_ = (int)__reduce_min_sync(0xffffffffu, ci2);
        // no second barrier: next step writes the other buffer
    }
}

// =====================================================================
// 2) Ball query: one warp per (b,s). First 32 ascending indices with d<=r^2,
//    padded with the first found index. Early exit.
// =====================================================================
__global__ __launch_bounds__(128)
void ballquery_kernel(const float* __restrict__ xyz, const float* __restrict__ newxyz)
{
    const int w    = (blockIdx.x * 128 + threadIdx.x) >> 5;
    const int lane = threadIdx.x & 31;
    const int b = w >> 10, s = w & 1023;

    const float* nx = newxyz + ((size_t)(b*SPOINT + s))*3;
    const float cx = nx[0], cy = nx[1], cz = nx[2];
    const float r2 = 0.04f;
    const float* base = xyz + (size_t)b*NPTS*3;
    int* dst = g_ballidx + (size_t)w*KSAMP;

    int cnt = 0, first = 0;
    for (int b0 = 0; b0 < NPTS; b0 += 32) {
        int p = b0 + lane;
        float dx = cx - base[p*3+0];
        float dy = cy - base[p*3+1];
        float dz = cz - base[p*3+2];
        float d = __fadd_rn(__fadd_rn(__fmul_rn(dx,dx), __fmul_rn(dy,dy)),
                            __fmul_rn(dz,dz));
        bool in = !(d > r2);
        unsigned mask = __ballot_sync(0xffffffffu, in);
        if (cnt == 0 && mask) first = b0 + __ffs(mask) - 1;
        int pos = cnt + __popc(mask & ((1u << lane) - 1u));
        if (in && pos < KSAMP) dst[pos] = p;
        cnt += __popc(mask);
        if (cnt >= KSAMP) break;
    }
    if (cnt < KSAMP && lane < KSAMP - cnt) dst[cnt + lane] = first;
}

// =====================================================================
// GEMM: 128x64 tile, 128 threads, 8x8 register blocking. NO occupancy
// floor -> no register spills.
// =====================================================================

// ---- layer 0: gather prologue (xyz,points,ballidx), K=67 ----
__global__ __launch_bounds__(128)
void gemm0_kernel(const float* __restrict__ xyz, const float* __restrict__ points,
                  const float* __restrict__ w0, const float* __restrict__ b0,
                  const float* __restrict__ newxyz)
{
    extern __shared__ float sm[];
    float* As = sm;                 // [67][132]
    float* Bs = sm + CIN*132;       // [67][64]

    const int tid  = threadIdx.x;
    const int row0 = blockIdx.x * 128;

    for (int i = tid; i < CIN*64; i += 128) {
        int k = i >> 6, oo = i & 63;
        Bs[k*64 + oo] = w0[oo*CIN + k];
    }
#pragma unroll
    for (int rr = 0; rr < 2; rr++) {
        int r = (tid >> 1) + rr*64;
        int half = tid & 1;
        int row = row0 + r;
        int bb = row >> 15;
        int ss = (row >> 5) & 1023;
        int idx = g_ballidx[row];
        const float* prow = points + ((size_t)(bb*NPTS + idx))*CFEAT;
#pragma unroll
        for (int j = 0; j < 8; j++) {
            int c = half*32 + j*4;
            float4 v = *(const float4*)(prow + c);
            As[(3+c+0)*132 + r] = v.x;
            As[(3+c+1)*132 + r] = v.y;
            As[(3+c+2)*132 + r] = v.z;
            As[(3+c+3)*132 + r] = v.w;
        }
        if (half == 0) {
            const float* pxyz = xyz + ((size_t)(bb*NPTS + idx))*3;
            const float* nx = newxyz + ((size_t)(bb*SPOINT + ss))*3;
            As[0*132 + r] = (pxyz[0]-nx[0]) / 0.2f;
            As[1*132 + r] = (pxyz[1]-nx[1]) / 0.2f;
            As[2*132 + r] = (pxyz[2]-nx[2]) / 0.2f;
        }
    }
    __syncthreads();

    const int cx = tid & 7, ry = tid >> 3;
    float acc[8][8];
#pragma unroll
    for (int i=0;i<8;i++)
#pragma unroll
        for (int j=0;j<8;j++) acc[i][j]=0.f;

#pragma unroll 4
    for (int k = 0; k < CIN; k++) {
        float4 a0 = *(const float4*)&As[k*132 + ry*8];
        float4 a1 = *(const float4*)&As[k*132 + ry*8 + 4];
        float4 c0 = *(const float4*)&Bs[k*64 + cx*8];
        float4 c1 = *(const float4*)&Bs[k*64 + cx*8 + 4];
        float av[8] = {a0.x,a0.y,a0.z,a0.w,a1.x,a1.y,a1.z,a1.w};
        float bv[8] = {c0.x,c0.y,c0.z,c0.w,c1.x,c1.y,c1.z,c1.w};
#pragma unroll
        for (int i=0;i<8;i++)
#pragma unroll
            for (int j=0;j<8;j++) acc[i][j] = fmaf(av[i], bv[j], acc[i][j]);
    }

    float bias[8], s8[8], q8[8];
#pragma unroll
    for (int j=0;j<8;j++){ bias[j]=b0[cx*8+j]; s8[j]=0.f; q8[j]=0.f; }
#pragma unroll
    for (int i=0;i<8;i++){
        float v[8];
#pragma unroll
        for (int j=0;j<8;j++){ v[j]=acc[i][j]+bias[j]; s8[j]+=v[j]; q8[j]=fmaf(v[j],v[j],q8[j]); }
        size_t row = (size_t)(row0 + ry*8 + i);
        *(float4*)&g_h0[row*64 + cx*8]     = make_float4(v[0],v[1],v[2],v[3]);
        *(float4*)&g_h0[row*64 + cx*8 + 4] = make_float4(v[4],v[5],v[6],v[7]);
    }
    const int lane = tid & 31, warp = tid >> 5;
#pragma unroll
    for (int j=0;j<8;j++){
        s8[j] += __shfl_xor_sync(0xffffffffu, s8[j], 8);
        s8[j] += __shfl_xor_sync(0xffffffffu, s8[j], 16);
        q8[j] += __shfl_xor_sync(0xffffffffu, q8[j], 8);
        q8[j] += __shfl_xor_sync(0xffffffffu, q8[j], 16);
    }
    __syncthreads();                       // smem reuse barrier
    float* sred  = sm;                     // [4][64]
    float* sqred = sm + 256;               // [4][64]
    if (lane < 8) {
#pragma unroll
        for (int j=0;j<8;j++){
            sred [warp*64 + lane*8 + j] = s8[j];
            sqred[warp*64 + lane*8 + j] = q8[j];
        }
    }
    __syncthreads();
    if (tid < 64) {
        g_psum[blockIdx.x*64 + tid] = sred [tid] + sred [64+tid] + sred [128+tid] + sred [192+tid];
        g_psq [blockIdx.x*64 + tid] = sqred[tid] + sqred[64+tid] + sqred[128+tid] + sqred[192+tid];
    }
}

// ---- layer 1: relu(affine(h0)) prologue, K=64, N=64 ----
__global__ __launch_bounds__(128)
void gemm1_kernel(const float* __restrict__ w, const float* __restrict__ bb)
{
    extern __shared__ float sm[];
    float* As = sm;                 // [64][132]
    float* Bs = sm + 64*132;        // [64][64]

    const int tid  = threadIdx.x;
    const int row0 = blockIdx.x * 128;

    for (int i = tid; i < 64*64; i += 128) {
        int k = i >> 6, oo = i & 63;
        Bs[k*64 + oo] = w[oo*64 + k];
    }
    {
        const int c4 = (tid & 15) * 4, rb = tid >> 4;
        float4 a4 = *(const float4*)&g_scale[0][c4];
        float4 s4 = *(const float4*)&g_shift[0][c4];
#pragma unroll 4
        for (int rr = 0; rr < 16; rr++) {
            int r = rb + rr*8;
            float4 v = *(const float4*)&g_h0[(size_t)(row0+r)*64 + c4];
            As[(c4+0)*132 + r] = fmaxf(0.f, fmaf(a4.x, v.x, s4.x));
            As[(c4+1)*132 + r] = fmaxf(0.f, fmaf(a4.y, v.y, s4.y));
            As[(c4+2)*132 + r] = fmaxf(0.f, fmaf(a4.z, v.z, s4.z));
            As[(c4+3)*132 + r] = fmaxf(0.f, fmaf(a4.w, v.w, s4.w));
        }
    }
    __syncthreads();

    const int cx = tid & 7, ry = tid >> 3;
    float acc[8][8];
#pragma unroll
    for (int i=0;i<8;i++)
#pragma unroll
        for (int j=0;j<8;j++) acc[i][j]=0.f;

#pragma unroll 4
    for (int k = 0; k < 64; k++) {
        float4 a0 = *(const float4*)&As[k*132 + ry*8];
        float4 a1 = *(const float4*)&As[k*132 + ry*8 + 4];
        float4 c0 = *(const float4*)&Bs[k*64 + cx*8];
        float4 c1 = *(const float4*)&Bs[k*64 + cx*8 + 4];
        float av[8] = {a0.x,a0.y,a0.z,a0.w,a1.x,a1.y,a1.z,a1.w};
        float bv[8] = {c0.x,c0.y,c0.z,c0.w,c1.x,c1.y,c1.z,c1.w};
#pragma unroll
        for (int i=0;i<8;i++)
#pragma unroll
            for (int j=0;j<8;j++) acc[i][j] = fmaf(av[i], bv[j], acc[i][j]);
    }

    float bias[8], s8[8], q8[8];
#pragma unroll
    for (int j=0;j<8;j++){ bias[j]=bb[cx*8+j]; s8[j]=0.f; q8[j]=0.f; }
#pragma unroll
    for (int i=0;i<8;i++){
        float v[8];
#pragma unroll
        for (int j=0;j<8;j++){ v[j]=acc[i][j]+bias[j]; s8[j]+=v[j]; q8[j]=fmaf(v[j],v[j],q8[j]); }
        size_t row = (size_t)(row0 + ry*8 + i);
        *(float4*)&g_h1[row*64 + cx*8]     = make_float4(v[0],v[1],v[2],v[3]);
        *(float4*)&g_h1[row*64 + cx*8 + 4] = make_float4(v[4],v[5],v[6],v[7]);
    }
    const int lane = tid & 31, warp = tid >> 5;
#pragma unroll
    for (int j=0;j<8;j++){
        s8[j] += __shfl_xor_sync(0xffffffffu, s8[j], 8);
        s8[j] += __shfl_xor_sync(0xffffffffu, s8[j], 16);
        q8[j] += __shfl_xor_sync(0xffffffffu, q8[j], 8);
        q8[j] += __shfl_xor_sync(0xffffffffu, q8[j], 16);
    }
    __syncthreads();
    float* sred  = sm;
    float* sqred = sm + 256;
    if (lane < 8) {
#pragma unroll
        for (int j=0;j<8;j++){
            sred [warp*64 + lane*8 + j] = s8[j];
            sqred[warp*64 + lane*8 + j] = q8[j];
        }
    }
    __syncthreads();
    if (tid < 64) {
        g_psum[blockIdx.x*64 + tid] = sred [tid] + sred [64+tid] + sred [128+tid] + sred [192+tid];
        g_psq [blockIdx.x*64 + tid] = sqred[tid] + sqred[64+tid] + sqred[128+tid] + sqred[192+tid];
    }
}

// ---- layer 2: relu(affine(h1)) prologue, K=64, N=128 (2 col blocks).
//      Epilogue: per-group max/min (group = 32 consecutive rows) + stats.
__global__ __launch_bounds__(128)
void gemm2_kernel(const float* __restrict__ w, const float* __restrict__ bb)
{
    extern __shared__ float sm[];
    float* As = sm;                 // [64][132]
    float* Bs = sm + 64*132;        // [64][64]

    const int tid   = threadIdx.x;
    const int row0  = blockIdx.x * 128;
    const int cblk  = blockIdx.y;          // 0/1 -> channels cblk*64..+63

    for (int i = tid; i < 64*64; i += 128) {
        int k = i >> 6, oo = i & 63;
        Bs[k*64 + oo] = w[(cblk*64 + oo)*64 + k];
    }
    {
        const int c4 = (tid & 15) * 4, rb = tid >> 4;
        float4 a4 = *(const float4*)&g_scale[1][c4];
        float4 s4 = *(const float4*)&g_shift[1][c4];
#pragma unroll 4
        for (int rr = 0; rr < 16; rr++) {
            int r = rb + rr*8;
            float4 v = *(const float4*)&g_h1[(size_t)(row0+r)*64 + c4];
            As[(c4+0)*132 + r] = fmaxf(0.f, fmaf(a4.x, v.x, s4.x));
            As[(c4+1)*132 + r] = fmaxf(0.f, fmaf(a4.y, v.y, s4.y));
            As[(c4+2)*132 + r] = fmaxf(0.f, fmaf(a4.z, v.z, s4.z));
            As[(c4+3)*132 + r] = fmaxf(0.f, fmaf(a4.w, v.w, s4.w));
        }
    }
    __syncthreads();

    const int cx = tid & 7, ry = tid >> 3;
    float acc[8][8];
#pragma unroll
    for (int i=0;i<8;i++)
#pragma unroll
        for (int j=0;j<8;j++) acc[i][j]=0.f;

#pragma unroll 4
    for (int k = 0; k < 64; k++) {
        float4 a0 = *(const float4*)&As[k*132 + ry*8];
        float4 a1 = *(const float4*)&As[k*132 + ry*8 + 4];
        float4 c0 = *(const float4*)&Bs[k*64 + cx*8];
        float4 c1 = *(const float4*)&Bs[k*64 + cx*8 + 4];
        float av[8] = {a0.x,a0.y,a0.z,a0.w,a1.x,a1.y,a1.z,a1.w};
        float bv[8] = {c0.x,c0.y,c0.z,c0.w,c1.x,c1.y,c1.z,c1.w};
#pragma unroll
        for (int i=0;i<8;i++)
#pragma unroll
            for (int j=0;j<8;j++) acc[i][j] = fmaf(av[i], bv[j], acc[i][j]);
    }

    float bias[8], s8[8], q8[8], mx[8], mn[8];
#pragma unroll
    for (int j=0;j<8;j++){
        bias[j]=bb[cblk*64 + cx*8 + j]; s8[j]=0.f; q8[j]=0.f;
        mx[j]=-3.4e38f; mn[j]=3.4e38f;
    }
#pragma unroll
    for (int i=0;i<8;i++){
#pragma unroll
        for (int j=0;j<8;j++){
            float v = acc[i][j]+bias[j];
            s8[j]+=v; q8[j]=fmaf(v,v,q8[j]);
            mx[j]=fmaxf(mx[j],v); mn[j]=fminf(mn[j],v);
        }
    }
    const int lane = tid & 31, warp = tid >> 5;
#pragma unroll
    for (int j=0;j<8;j++){
        s8[j] += __shfl_xor_sync(0xffffffffu, s8[j], 8);
        s8[j] += __shfl_xor_sync(0xffffffffu, s8[j], 16);
        q8[j] += __shfl_xor_sync(0xffffffffu, q8[j], 8);
        q8[j] += __shfl_xor_sync(0xffffffffu, q8[j], 16);
        mx[j] = fmaxf(mx[j], __shfl_xor_sync(0xffffffffu, mx[j], 8));
        mx[j] = fmaxf(mx[j], __shfl_xor_sync(0xffffffffu, mx[j], 16));
        mn[j] = fminf(mn[j], __shfl_xor_sync(0xffffffffu, mn[j], 8));
        mn[j] = fminf(mn[j], __shfl_xor_sync(0xffffffffu, mn[j], 16));
    }
    if (lane < 8) {
        size_t grp = (size_t)blockIdx.x*4 + warp;
#pragma unroll
        for (int j=0;j<8;j++){
            g_gmax[grp*128 + cblk*64 + lane*8 + j] = mx[j];
            g_gmin[grp*128 + cblk*64 + lane*8 + j] = mn[j];
        }
    }
    __syncthreads();
    float* sred  = sm;
    float* sqred = sm + 256;
    if (lane < 8) {
#pragma unroll
        for (int j=0;j<8;j++){
            sred [warp*64 + lane*8 + j] = s8[j];
            sqred[warp*64 + lane*8 + j] = q8[j];
        }
    }
    __syncthreads();
    if (tid < 64) {
        g_psum[blockIdx.x*128 + cblk*64 + tid] = sred [tid] + sred [64+tid] + sred [128+tid] + sred [192+tid];
        g_psq [blockIdx.x*128 + cblk*64 + tid] = sqred[tid] + sqred[64+tid] + sqred[128+tid] + sqred[192+tid];
    }
}

// =====================================================================
// Stats fold: one block per channel, 256 threads, deterministic strided
// partial sums + fixed-order tree reduction in double.
// =====================================================================
__global__ __launch_bounds__(256)
void stats_kernel(const float* __restrict__ g, const float* __restrict__ be,
                  int layer, int nch)
{
    __shared__ double ssum[256], ssq[256];
    const int ch = blockIdx.x;
    const int t  = threadIdx.x;

    double s = 0.0, q = 0.0;
    for (int b = t; b < NBLK; b += 256) {
        s += (double)g_psum[b*nch + ch];
        q += (double)g_psq [b*nch + ch];
    }
    ssum[t] = s; ssq[t] = q;
    __syncthreads();
#pragma unroll
    for (int off = 128; off > 0; off >>= 1) {
        if (t < off) { ssum[t] += ssum[t+off]; ssq[t] += ssq[t+off]; }
        __syncthreads();
    }
    if (t == 0) {
        const double M = (double)MROWS;
        double mu  = ssum[0] / M;
        double var = ssq[0] / M - mu*mu;
        float rs = (float)(1.0 / sqrt(var + 1e-5));
        float a  = g[ch] * rs;
        float c  = be[ch] - (float)mu * a;
        g_scale[layer][ch] = a;
        g_shift[layer][ch] = c;
    }
}

// =====================================================================
// Final: new_points[grp][ch] = relu(a * (a>=0 ? gmax : gmin) + c)
// =====================================================================
__global__ void final_kernel(float* __restrict__ out)
{
    int grp = blockIdx.x, ch = threadIdx.x;
    float a = g_scale[2][ch], c = g_shift[2][ch];
    float h = (a >= 0.f) ? g_gmax[(size_t)grp*128 + ch] : g_gmin[(size_t)grp*128 + ch];
    out[OUT_XYZ_ELEMS + (size_t)grp*128 + ch] = fmaxf(0.f, fmaf(a, h, c));
}

// =====================================================================
extern "C" void kernel_launch(void* const* d_in, const int* in_sizes, int n_in,
                              void* d_out, int out_size)
{
    const float* xyz    = (const float*)d_in[0];
    const float* points = (const float*)d_in[1];
    const float* w0  = (const float*)d_in[2];
    const float* b0  = (const float*)d_in[3];
    const float* g0  = (const float*)d_in[4];
    const float* be0 = (const float*)d_in[5];
    const float* w1  = (const float*)d_in[6];
    const float* b1  = (const float*)d_in[7];
    const float* g1  = (const float*)d_in[8];
    const float* be1 = (const float*)d_in[9];
    const float* w2  = (const float*)d_in[10];
    const float* b2  = (const float*)d_in[11];
    const float* g2  = (const float*)d_in[12];
    const float* be2 = (const float*)d_in[13];
    float* out = (float*)d_out;

    const int FPS_SM   = NPTS*3*4;           // 49152
    const int GEMM0_SM = CIN*(132+64)*4;     // 52528
    const int GEMM_SM  = 64*(132+64)*4;      // 50176
    cudaFuncSetAttribute(fps_kernel,   cudaFuncAttributeMaxDynamicSharedMemorySize, FPS_SM);
    cudaFuncSetAttribute(gemm0_kernel, cudaFuncAttributeMaxDynamicSharedMemorySize, GEMM0_SM);
    cudaFuncSetAttribute(gemm1_kernel, cudaFuncAttributeMaxDynamicSharedMemorySize, GEMM_SM);
    cudaFuncSetAttribute(gemm2_kernel, cudaFuncAttributeMaxDynamicSharedMemorySize, GEMM_SM);

    fps_kernel<<<BATCH, 1024, FPS_SM>>>(xyz, out);
    ballquery_kernel<<<(NGROUP*32)/128, 128>>>(xyz, out);
    gemm0_kernel<<<NBLK, 128, GEMM0_SM>>>(xyz, points, w0, b0, out);
    stats_kernel<<<64, 256>>>(g0, be0, 0, 64);
    gemm1_kernel<<<NBLK, 128, GEMM_SM>>>(w1, b1);
    stats_kernel<<<64, 256>>>(g1, be1, 1, 64);
    dim3 g2grid(NBLK, 2);
    gemm2_kernel<<<g2grid, 128, GEMM_SM>>>(w2, b2);
    stats_kernel<<<128, 256>>>(g2, be2, 2, 128);
    final_kernel<<<NGROUP, 128>>>(out);
}

// round 7
// speedup vs baseline: 4.3931x; 1.0946x over previous
#include <cuda_runtime.h>
#include <cuda_bf16.h>
#include <cstdint>
#include <math.h>

// ---------------- problem constants ----------------
#define BATCH    16
#define NPTS     4096
#define CFEAT    64
#define SPOINT   1024
#define KSAMP    32
#define CIN      67
#define MROWS    (BATCH*SPOINT*KSAMP)      // 524288
#define NGROUP   (BATCH*SPOINT)            // 16384
#define NBLK     (MROWS/128)               // 4096
#define OUT_XYZ_ELEMS (BATCH*SPOINT*3)     // 49152

// ---------------- device scratch (no allocs allowed) ----------------
__device__ int   g_ballidx[MROWS];
__device__ float g_h0[(size_t)MROWS*64];
__device__ float g_h1[(size_t)MROWS*64];
__device__ float g_gmax[(size_t)NGROUP*128];
__device__ float g_gmin[(size_t)NGROUP*128];
__device__ float g_psum[NBLK*128];
__device__ float g_psq [NBLK*128];
__device__ float g_scale[3][128];
__device__ float g_shift[3][128];

// ---------------- packed f32x2 helpers (Blackwell dual-FP32) ----------------
__device__ __forceinline__ unsigned long long pack2(float lo, float hi) {
    unsigned long long r;
    asm("mov.b64 %0, {%1,%2};" : "=l"(r) : "f"(lo), "f"(hi));
    return r;
}
__device__ __forceinline__ void unpack2(unsigned long long v, float& lo, float& hi) {
    asm("mov.b64 {%0,%1}, %2;" : "=f"(lo), "=f"(hi) : "l"(v));
}
__device__ __forceinline__ unsigned long long fma2(unsigned long long a,
                                                   unsigned long long b,
                                                   unsigned long long c) {
    unsigned long long d;
    asm("fma.rn.f32x2 %0, %1, %2, %3;" : "=l"(d) : "l"(a), "l"(b), "l"(c));
    return d;
}

// =====================================================================
// 1) FPS. One block/batch, 1024 threads, 4 pts/thread in registers.
//    One barrier per step via double-buffered warp maxima.
// =====================================================================
__global__ void fps_kernel(const float* __restrict__ xyz, float* __restrict__ out_xyz)
{
    extern __shared__ float sh[];            // sx[4096] sy[4096] sz[4096]
    float* sx = sh;
    float* sy = sh + NPTS;
    float* sz = sh + 2*NPTS;
    __shared__ float    wv[2][32];
    __shared__ unsigned wi[2][32];

    const int b = blockIdx.x, t = threadIdx.x;
    const int lane = t & 31, warp = t >> 5;
    const float* base = xyz + (size_t)b*NPTS*3;

    float px[4], py[4], pz[4], dist[4];
#pragma unroll
    for (int k = 0; k < 4; k++) {
        int p = t + k*1024;
        float x = base[p*3+0], y = base[p*3+1], z = base[p*3+2];
        px[k]=x; py[k]=y; pz[k]=z;
        sx[p]=x; sy[p]=y; sz[p]=z;
        dist[k] = 1e10f;
    }
    __syncthreads();

    int far_ = 0;
    float* o = out_xyz + (size_t)b*SPOINT*3;

    for (int i = 0; i < SPOINT; i++) {
        const int buf = i & 1;
        float cx = sx[far_], cy = sy[far_], cz = sz[far_];
        if (t == 0) { o[i*3+0] = cx; o[i*3+1] = cy; o[i*3+2] = cz; }

        float bestv = -1.0f; unsigned besti = 0u;
#pragma unroll
        for (int k = 0; k < 4; k++) {
            float dx = px[k]-cx, dy = py[k]-cy, dz = pz[k]-cz;
            float d = __fadd_rn(__fadd_rn(__fmul_rn(dx,dx), __fmul_rn(dy,dy)),
                                __fmul_rn(dz,dz));
            float nd = fminf(dist[k], d);
            dist[k] = nd;
            if (nd > bestv) { bestv = nd; besti = (unsigned)(t + k*1024); }
        }
        unsigned uv = __float_as_uint(bestv);
        unsigned mv = __reduce_max_sync(0xffffffffu, uv);
        unsigned ci = (uv == mv) ? besti : 0xffffffffu;
        unsigned mi = __reduce_min_sync(0xffffffffu, ci);
        if (lane == 0) { wv[buf][warp] = __uint_as_float(mv); wi[buf][warp] = mi; }
        __syncthreads();
        unsigned uv2 = __float_as_uint(wv[buf][lane]);
        unsigned mv2 = __reduce_max_sync(0xffffffffu, uv2);
        unsigned ci2 = (uv2 == mv2) ? wi[buf][lane] : 0xffffffffu;
        far_ = (int)__reduce_min_sync(0xffffffffu, ci2);
    }
}

// =====================================================================
// 2) Ball query: one warp per (b,s).
// =====================================================================
__global__ __launch_bounds__(128)
void ballquery_kernel(const float* __restrict__ xyz, const float* __restrict__ newxyz)
{
    const int w    = (blockIdx.x * 128 + threadIdx.x) >> 5;
    const int lane = threadIdx.x & 31;
    const int b = w >> 10, s = w & 1023;

    const float* nx = newxyz + ((size_t)(b*SPOINT + s))*3;
    const float cx = nx[0], cy = nx[1], cz = nx[2];
    const float r2 = 0.04f;
    const float* base = xyz + (size_t)b*NPTS*3;
    int* dst = g_ballidx + (size_t)w*KSAMP;

    int cnt = 0, first = 0;
    for (int b0 = 0; b0 < NPTS; b0 += 32) {
        int p = b0 + lane;
        float dx = cx - base[p*3+0];
        float dy = cy - base[p*3+1];
        float dz = cz - base[p*3+2];
        float d = __fadd_rn(__fadd_rn(__fmul_rn(dx,dx), __fmul_rn(dy,dy)),
                            __fmul_rn(dz,dz));
        bool in = !(d > r2);
        unsigned mask = __ballot_sync(0xffffffffu, in);
        if (cnt == 0 && mask) first = b0 + __ffs(mask) - 1;
        int pos = cnt + __popc(mask & ((1u << lane) - 1u));
        if (in && pos < KSAMP) dst[pos] = p;
        cnt += __popc(mask);
        if (cnt >= KSAMP) break;
    }
    if (cnt < KSAMP && lane < KSAMP - cnt) dst[cnt + lane] = first;
}

// =====================================================================
// GEMM 0/1: 128x64 tile, 128 threads, 8x8 register blocking, f32x2 FMA.
// =====================================================================

// ---- layer 0: gather prologue (xyz,points,ballidx), K=67 ----
__global__ __launch_bounds__(128)
void gemm0_kernel(const float* __restrict__ xyz, const float* __restrict__ points,
                  const float* __restrict__ w0, const float* __restrict__ b0,
                  const float* __restrict__ newxyz)
{
    extern __shared__ float sm[];
    float* As = sm;                 // [67][132]
    float* Bs = sm + CIN*132;       // [67][64]

    const int tid  = threadIdx.x;
    const int row0 = blockIdx.x * 128;

    for (int i = tid; i < CIN*64; i += 128) {
        int k = i >> 6, oo = i & 63;
        Bs[k*64 + oo] = w0[oo*CIN + k];
    }
#pragma unroll
    for (int rr = 0; rr < 2; rr++) {
        int r = (tid >> 1) + rr*64;
        int half = tid & 1;
        int row = row0 + r;
        int bb = row >> 15;
        int ss = (row >> 5) & 1023;
        int idx = g_ballidx[row];
        const float* prow = points + ((size_t)(bb*NPTS + idx))*CFEAT;
#pragma unroll
        for (int j = 0; j < 8; j++) {
            int c = half*32 + j*4;
            float4 v = *(const float4*)(prow + c);
            As[(3+c+0)*132 + r] = v.x;
            As[(3+c+1)*132 + r] = v.y;
            As[(3+c+2)*132 + r] = v.z;
            As[(3+c+3)*132 + r] = v.w;
        }
        if (half == 0) {
            const float* pxyz = xyz + ((size_t)(bb*NPTS + idx))*3;
            const float* nx = newxyz + ((size_t)(bb*SPOINT + ss))*3;
            As[0*132 + r] = (pxyz[0]-nx[0]) / 0.2f;
            As[1*132 + r] = (pxyz[1]-nx[1]) / 0.2f;
            As[2*132 + r] = (pxyz[2]-nx[2]) / 0.2f;
        }
    }
    __syncthreads();

    const int cx = tid & 7, ry = tid >> 3;
    unsigned long long acc2[8][4];
#pragma unroll
    for (int i=0;i<8;i++)
#pragma unroll
        for (int j=0;j<4;j++) acc2[i][j]=0ULL;

#pragma unroll 4
    for (int k = 0; k < CIN; k++) {
        float4 a0 = *(const float4*)&As[k*132 + ry*8];
        float4 a1 = *(const float4*)&As[k*132 + ry*8 + 4];
        float4 c0 = *(const float4*)&Bs[k*64 + cx*8];
        float4 c1 = *(const float4*)&Bs[k*64 + cx*8 + 4];
        unsigned long long bp[4] = {pack2(c0.x,c0.y), pack2(c0.z,c0.w),
                                    pack2(c1.x,c1.y), pack2(c1.z,c1.w)};
        float av[8] = {a0.x,a0.y,a0.z,a0.w,a1.x,a1.y,a1.z,a1.w};
#pragma unroll
        for (int i=0;i<8;i++){
            unsigned long long aa = pack2(av[i], av[i]);
#pragma unroll
            for (int j=0;j<4;j++) acc2[i][j] = fma2(aa, bp[j], acc2[i][j]);
        }
    }

    float bias[8], s8[8], q8[8];
#pragma unroll
    for (int j=0;j<8;j++){ bias[j]=b0[cx*8+j]; s8[j]=0.f; q8[j]=0.f; }
#pragma unroll
    for (int i=0;i<8;i++){
        float v[8];
#pragma unroll
        for (int j=0;j<4;j++) unpack2(acc2[i][j], v[2*j], v[2*j+1]);
#pragma unroll
        for (int j=0;j<8;j++){ v[j]+=bias[j]; s8[j]+=v[j]; q8[j]=fmaf(v[j],v[j],q8[j]); }
        size_t row = (size_t)(row0 + ry*8 + i);
        *(float4*)&g_h0[row*64 + cx*8]     = make_float4(v[0],v[1],v[2],v[3]);
        *(float4*)&g_h0[row*64 + cx*8 + 4] = make_float4(v[4],v[5],v[6],v[7]);
    }
    const int lane = tid & 31, warp = tid >> 5;
#pragma unroll
    for (int j=0;j<8;j++){
        s8[j] += __shfl_xor_sync(0xffffffffu, s8[j], 8);
        s8[j] += __shfl_xor_sync(0xffffffffu, s8[j], 16);
        q8[j] += __shfl_xor_sync(0xffffffffu, q8[j], 8);
        q8[j] += __shfl_xor_sync(0xffffffffu, q8[j], 16);
    }
    __syncthreads();
    float* sred  = sm;
    float* sqred = sm + 256;
    if (lane < 8) {
#pragma unroll
        for (int j=0;j<8;j++){
            sred [warp*64 + lane*8 + j] = s8[j];
            sqred[warp*64 + lane*8 + j] = q8[j];
        }
    }
    __syncthreads();
    if (tid < 64) {
        g_psum[blockIdx.x*64 + tid] = sred [tid] + sred [64+tid] + sred [128+tid] + sred [192+tid];
        g_psq [blockIdx.x*64 + tid] = sqred[tid] + sqred[64+tid] + sqred[128+tid] + sqred[192+tid];
    }
}

// ---- layer 1: relu(affine(h0)) prologue, K=64, N=64 ----
__global__ __launch_bounds__(128)
void gemm1_kernel(const float* __restrict__ w, const float* __restrict__ bb)
{
    extern __shared__ float sm[];
    float* As = sm;                 // [64][132]
    float* Bs = sm + 64*132;        // [64][64]

    const int tid  = threadIdx.x;
    const int row0 = blockIdx.x * 128;

    for (int i = tid; i < 64*64; i += 128) {
        int k = i >> 6, oo = i & 63;
        Bs[k*64 + oo] = w[oo*64 + k];
    }
    {
        const int c4 = (tid & 15) * 4, rb = tid >> 4;
        float4 a4 = *(const float4*)&g_scale[0][c4];
        float4 s4 = *(const float4*)&g_shift[0][c4];
#pragma unroll 4
        for (int rr = 0; rr < 16; rr++) {
            int r = rb + rr*8;
            float4 v = *(const float4*)&g_h0[(size_t)(row0+r)*64 + c4];
            As[(c4+0)*132 + r] = fmaxf(0.f, fmaf(a4.x, v.x, s4.x));
            As[(c4+1)*132 + r] = fmaxf(0.f, fmaf(a4.y, v.y, s4.y));
            As[(c4+2)*132 + r] = fmaxf(0.f, fmaf(a4.z, v.z, s4.z));
            As[(c4+3)*132 + r] = fmaxf(0.f, fmaf(a4.w, v.w, s4.w));
        }
    }
    __syncthreads();

    const int cx = tid & 7, ry = tid >> 3;
    unsigned long long acc2[8][4];
#pragma unroll
    for (int i=0;i<8;i++)
#pragma unroll
        for (int j=0;j<4;j++) acc2[i][j]=0ULL;

#pragma unroll 4
    for (int k = 0; k < 64; k++) {
        float4 a0 = *(const float4*)&As[k*132 + ry*8];
        float4 a1 = *(const float4*)&As[k*132 + ry*8 + 4];
        float4 c0 = *(const float4*)&Bs[k*64 + cx*8];
        float4 c1 = *(const float4*)&Bs[k*64 + cx*8 + 4];
        unsigned long long bp[4] = {pack2(c0.x,c0.y), pack2(c0.z,c0.w),
                                    pack2(c1.x,c1.y), pack2(c1.z,c1.w)};
        float av[8] = {a0.x,a0.y,a0.z,a0.w,a1.x,a1.y,a1.z,a1.w};
#pragma unroll
        for (int i=0;i<8;i++){
            unsigned long long aa = pack2(av[i], av[i]);
#pragma unroll
            for (int j=0;j<4;j++) acc2[i][j] = fma2(aa, bp[j], acc2[i][j]);
        }
    }

    float bias[8], s8[8], q8[8];
#pragma unroll
    for (int j=0;j<8;j++){ bias[j]=bb[cx*8+j]; s8[j]=0.f; q8[j]=0.f; }
#pragma unroll
    for (int i=0;i<8;i++){
        float v[8];
#pragma unroll
        for (int j=0;j<4;j++) unpack2(acc2[i][j], v[2*j], v[2*j+1]);
#pragma unroll
        for (int j=0;j<8;j++){ v[j]+=bias[j]; s8[j]+=v[j]; q8[j]=fmaf(v[j],v[j],q8[j]); }
        size_t row = (size_t)(row0 + ry*8 + i);
        *(float4*)&g_h1[row*64 + cx*8]     = make_float4(v[0],v[1],v[2],v[3]);
        *(float4*)&g_h1[row*64 + cx*8 + 4] = make_float4(v[4],v[5],v[6],v[7]);
    }
    const int lane = tid & 31, warp = tid >> 5;
#pragma unroll
    for (int j=0;j<8;j++){
        s8[j] += __shfl_xor_sync(0xffffffffu, s8[j], 8);
        s8[j] += __shfl_xor_sync(0xffffffffu, s8[j], 16);
        q8[j] += __shfl_xor_sync(0xffffffffu, q8[j], 8);
        q8[j] += __shfl_xor_sync(0xffffffffu, q8[j], 16);
    }
    __syncthreads();
    float* sred  = sm;
    float* sqred = sm + 256;
    if (lane < 8) {
#pragma unroll
        for (int j=0;j<8;j++){
            sred [warp*64 + lane*8 + j] = s8[j];
            sqred[warp*64 + lane*8 + j] = q8[j];
        }
    }
    __syncthreads();
    if (tid < 64) {
        g_psum[blockIdx.x*64 + tid] = sred [tid] + sred [64+tid] + sred [128+tid] + sred [192+tid];
        g_psq [blockIdx.x*64 + tid] = sqred[tid] + sqred[64+tid] + sqred[128+tid] + sqred[192+tid];
    }
}

// ---- layer 2 (merged): 128x128 tile, 256 threads, K=64, f32x2.
//      Epilogue: per-group (32-row) max/min + per-block channel stats.
__global__ __launch_bounds__(256)
void gemm2_kernel(const float* __restrict__ w, const float* __restrict__ bb)
{
    extern __shared__ float sm[];
    float* As = sm;                 // [64][132]  (132*64 floats)
    float* Bs = sm + 64*132;        // [64][128]

    const int tid  = threadIdx.x;
    const int row0 = blockIdx.x * 128;

    for (int i = tid; i < 64*128; i += 256) {
        int k = i >> 7, oo = i & 127;
        Bs[k*128 + oo] = w[oo*64 + k];
    }
    {
        const int c4 = (tid & 15) * 4, rb = tid >> 4;   // rb in 0..15
        float4 a4 = *(const float4*)&g_scale[1][c4];
        float4 s4 = *(const float4*)&g_shift[1][c4];
#pragma unroll 4
        for (int rr = 0; rr < 8; rr++) {
            int r = rb + rr*16;
            float4 v = *(const float4*)&g_h1[(size_t)(row0+r)*64 + c4];
            As[(c4+0)*132 + r] = fmaxf(0.f, fmaf(a4.x, v.x, s4.x));
            As[(c4+1)*132 + r] = fmaxf(0.f, fmaf(a4.y, v.y, s4.y));
            As[(c4+2)*132 + r] = fmaxf(0.f, fmaf(a4.z, v.z, s4.z));
            As[(c4+3)*132 + r] = fmaxf(0.f, fmaf(a4.w, v.w, s4.w));
        }
    }
    __syncthreads();

    const int cx = tid & 15, ry = tid >> 4;   // cols cx*8..+7 (of 128), rows ry*8..+7
    unsigned long long acc2[8][4];
#pragma unroll
    for (int i=0;i<8;i++)
#pragma unroll
        for (int j=0;j<4;j++) acc2[i][j]=0ULL;

#pragma unroll 2
    for (int k = 0; k < 64; k++) {
        float4 a0 = *(const float4*)&As[k*132 + ry*8];
        float4 a1 = *(const float4*)&As[k*132 + ry*8 + 4];
        float4 c0 = *(const float4*)&Bs[k*128 + cx*8];
        float4 c1 = *(const float4*)&Bs[k*128 + cx*8 + 4];
        unsigned long long bp[4] = {pack2(c0.x,c0.y), pack2(c0.z,c0.w),
                                    pack2(c1.x,c1.y), pack2(c1.z,c1.w)};
        float av[8] = {a0.x,a0.y,a0.z,a0.w,a1.x,a1.y,a1.z,a1.w};
#pragma unroll
        for (int i=0;i<8;i++){
            unsigned long long aa = pack2(av[i], av[i]);
#pragma unroll
            for (int j=0;j<4;j++) acc2[i][j] = fma2(aa, bp[j], acc2[i][j]);
        }
    }

    float bias[8], s8[8], q8[8], mx[8], mn[8];
#pragma unroll
    for (int j=0;j<8;j++){
        bias[j]=bb[cx*8+j]; s8[j]=0.f; q8[j]=0.f;
        mx[j]=-3.4e38f; mn[j]=3.4e38f;
    }
#pragma unroll
    for (int i=0;i<8;i++){
        float v[8];
#pragma unroll
        for (int j=0;j<4;j++) unpack2(acc2[i][j], v[2*j], v[2*j+1]);
#pragma unroll
        for (int j=0;j<8;j++){
            v[j]+=bias[j];
            s8[j]+=v[j]; q8[j]=fmaf(v[j],v[j],q8[j]);
            mx[j]=fmaxf(mx[j],v[j]); mn[j]=fminf(mn[j],v[j]);
        }
    }
    const int lane = tid & 31, warp = tid >> 5;   // warp covers rows warp*16..+15
    // fold lane ^16 (same cx, adjacent ry)
#pragma unroll
    for (int j=0;j<8;j++){
        s8[j] += __shfl_xor_sync(0xffffffffu, s8[j], 16);
        q8[j] += __shfl_xor_sync(0xffffffffu, q8[j], 16);
        mx[j] = fmaxf(mx[j], __shfl_xor_sync(0xffffffffu, mx[j], 16));
        mn[j] = fminf(mn[j], __shfl_xor_sync(0xffffffffu, mn[j], 16));
    }
    __syncthreads();                 // smem reuse barrier
    float* sred  = sm;               // [8][128]
    float* sqred = sm + 1024;        // [8][128]
    float* smax  = sm + 2048;        // [8][128]
    float* smin  = sm + 3072;        // [8][128]
    if (lane < 16) {
#pragma unroll
        for (int j=0;j<8;j++){
            sred [warp*128 + lane*8 + j] = s8[j];
            sqred[warp*128 + lane*8 + j] = q8[j];
            smax [warp*128 + lane*8 + j] = mx[j];
            smin [warp*128 + lane*8 + j] = mn[j];
        }
    }
    __syncthreads();
    // channel stats: fixed order over 8 warps
    if (tid < 128) {
        float ts = 0.f, tq = 0.f;
#pragma unroll
        for (int wgt = 0; wgt < 8; wgt++) { ts += sred[wgt*128 + tid]; tq += sqred[wgt*128 + tid]; }
        g_psum[blockIdx.x*128 + tid] = ts;
        g_psq [blockIdx.x*128 + tid] = tq;
    }
    // group max/min: group g (rows g*32..+31) = warps 2g, 2g+1
    {
        int c = tid & 127;
        int gbase = (tid >> 7) * 2;     // 0 or 2
#pragma unroll
        for (int gg = 0; gg < 2; gg++) {
            int g = gbase + gg;
            float vmx = fmaxf(smax[(2*g)*128 + c], smax[(2*g+1)*128 + c]);
            float vmn = fminf(smin[(2*g)*128 + c], smin[(2*g+1)*128 + c]);
            size_t grp = (size_t)blockIdx.x*4 + g;
            g_gmax[grp*128 + c] = vmx;
            g_gmin[grp*128 + c] = vmn;
        }
    }
}

// =====================================================================
// Stats fold: one block per channel, deterministic order.
// =====================================================================
__global__ __launch_bounds__(256)
void stats_kernel(const float* __restrict__ g, const float* __restrict__ be,
                  int layer, int nch)
{
    __shared__ double ssum[256], ssq[256];
    const int ch = blockIdx.x;
    const int t  = threadIdx.x;

    double s = 0.0, q = 0.0;
    for (int b = t; b < NBLK; b += 256) {
        s += (double)g_psum[b*nch + ch];
        q += (double)g_psq [b*nch + ch];
    }
    ssum[t] = s; ssq[t] = q;
    __syncthreads();
#pragma unroll
    for (int off = 128; off > 0; off >>= 1) {
        if (t < off) { ssum[t] += ssum[t+off]; ssq[t] += ssq[t+off]; }
        __syncthreads();
    }
    if (t == 0) {
        const double M = (double)MROWS;
        double mu  = ssum[0] / M;
        double var = ssq[0] / M - mu*mu;
        float rs = (float)(1.0 / sqrt(var + 1e-5));
        float a  = g[ch] * rs;
        float c  = be[ch] - (float)mu * a;
        g_scale[layer][ch] = a;
        g_shift[layer][ch] = c;
    }
}

// =====================================================================
// Final: new_points[grp][ch] = relu(a * (a>=0 ? gmax : gmin) + c)
// =====================================================================
__global__ void final_kernel(float* __restrict__ out)
{
    int grp = blockIdx.x, ch = threadIdx.x;
    float a = g_scale[2][ch], c = g_shift[2][ch];
    float h = (a >= 0.f) ? g_gmax[(size_t)grp*128 + ch] : g_gmin[(size_t)grp*128 + ch];
    out[OUT_XYZ_ELEMS + (size_t)grp*128 + ch] = fmaxf(0.f, fmaf(a, h, c));
}

// =====================================================================
extern "C" void kernel_launch(void* const* d_in, const int* in_sizes, int n_in,
                              void* d_out, int out_size)
{
    const float* xyz    = (const float*)d_in[0];
    const float* points = (const float*)d_in[1];
    const float* w0  = (const float*)d_in[2];
    const float* b0  = (const float*)d_in[3];
    const float* g0  = (const float*)d_in[4];
    const float* be0 = (const float*)d_in[5];
    const float* w1  = (const float*)d_in[6];
    const float* b1  = (const float*)d_in[7];
    const float* g1  = (const float*)d_in[8];
    const float* be1 = (const float*)d_in[9];
    const float* w2  = (const float*)d_in[10];
    const float* b2  = (const float*)d_in[11];
    const float* g2  = (const float*)d_in[12];
    const float* be2 = (const float*)d_in[13];
    float* out = (float*)d_out;

    const int FPS_SM   = NPTS*3*4;            // 49152
    const int GEMM0_SM = CIN*(132+64)*4;      // 52528
    const int GEMM_SM  = 64*(132+64)*4;       // 50176
    const int GEMM2_SM = 64*(132+128)*4;      // 66560
    cudaFuncSetAttribute(fps_kernel,   cudaFuncAttributeMaxDynamicSharedMemorySize, FPS_SM);
    cudaFuncSetAttribute(gemm0_kernel, cudaFuncAttributeMaxDynamicSharedMemorySize, GEMM0_SM);
    cudaFuncSetAttribute(gemm1_kernel, cudaFuncAttributeMaxDynamicSharedMemorySize, GEMM_SM);
    cudaFuncSetAttribute(gemm2_kernel, cudaFuncAttributeMaxDynamicSharedMemorySize, GEMM2_SM);

    fps_kernel<<<BATCH, 1024, FPS_SM>>>(xyz, out);
    ballquery_kernel<<<(NGROUP*32)/128, 128>>>(xyz, out);
    gemm0_kernel<<<NBLK, 128, GEMM0_SM>>>(xyz, points, w0, b0, out);
    stats_kernel<<<64, 256>>>(g0, be0, 0, 64);
    gemm1_kernel<<<NBLK, 128, GEMM_SM>>>(w1, b1);
    stats_kernel<<<64, 256>>>(g1, be1, 1, 64);
    gemm2_kernel<<<NBLK, 256, GEMM2_SM>>>(w2, b2);
    stats_kernel<<<128, 256>>>(g2, be2, 2, 128);
    final_kernel<<<NGROUP, 128>>>(out);
}

// round 10
// speedup vs baseline: 5.3964x; 1.2284x over previous
#include <cuda_runtime.h>
#include <cuda_bf16.h>
#include <cstdint>
#include <math.h>

// ---------------- problem constants ----------------
#define BATCH    16
#define NPTS     4096
#define CFEAT    64
#define SPOINT   1024
#define KSAMP    32
#define CIN      67
#define MROWS    (BATCH*SPOINT*KSAMP)      // 524288
#define NGROUP   (BATCH*SPOINT)            // 16384
#define NBLK     (MROWS/128)               // 4096
#define OUT_XYZ_ELEMS (BATCH*SPOINT*3)     // 49152
#define ASTRIDE  144                        // bytes per padded bf16 row (72 halves)

// ---------------- device scratch ----------------
__device__ int   g_ballidx[MROWS];
__device__ float g_h0[(size_t)MROWS*64];
__device__ float g_h1[(size_t)MROWS*64];
__device__ float g_gmax[(size_t)NGROUP*128];
__device__ float g_gmin[(size_t)NGROUP*128];
__device__ float g_psum[NBLK*128];
__device__ float g_psq [NBLK*128];
__device__ float g_scale[3][128];
__device__ float g_shift[3][128];

// ---------------- helpers ----------------
__device__ __forceinline__ uint32_t smem_u32(const void* p) {
    uint32_t a;
    asm("{ .reg .u64 t; cvta.to.shared.u64 t, %1; cvt.u32.u64 %0, t; }" : "=r"(a) : "l"(p));
    return a;
}
__device__ __forceinline__ void ldsm_x4(uint32_t* r, uint32_t addr) {
    asm volatile("ldmatrix.sync.aligned.m8n8.x4.shared.b16 {%0,%1,%2,%3}, [%4];"
                 : "=r"(r[0]), "=r"(r[1]), "=r"(r[2]), "=r"(r[3]) : "r"(addr));
}
__device__ __forceinline__ void mma16816(float* d, const uint32_t* a, const uint32_t* b) {
    asm volatile(
        "mma.sync.aligned.m16n8k16.row.col.f32.bf16.bf16.f32 "
        "{%0,%1,%2,%3}, {%4,%5,%6,%7}, {%8,%9}, {%0,%1,%2,%3};"
        : "+f"(d[0]), "+f"(d[1]), "+f"(d[2]), "+f"(d[3])
        : "r"(a[0]), "r"(a[1]), "r"(a[2]), "r"(a[3]), "r"(b[0]), "r"(b[1]));
}
// split x into bf16 hi + lo, packed pair-wise into u32
__device__ __forceinline__ void split_pack(float a0, float a1, uint32_t& whi, uint32_t& wlo) {
    __nv_bfloat16 h0 = __float2bfloat16(a0), h1 = __float2bfloat16(a1);
    float r0 = a0 - __bfloat162float(h0), r1 = a1 - __bfloat162float(h1);
    __nv_bfloat16 l0 = __float2bfloat16(r0), l1 = __float2bfloat16(r1);
    whi = ((uint32_t)__bfloat16_as_ushort(h1) << 16) | __bfloat16_as_ushort(h0);
    wlo = ((uint32_t)__bfloat16_as_ushort(l1) << 16) | __bfloat16_as_ushort(l0);
}

// =====================================================================
// 1) FPS (unchanged)
// =====================================================================
__global__ void fps_kernel(const float* __restrict__ xyz, float* __restrict__ out_xyz)
{
    extern __shared__ float sh[];
    float* sx = sh;
    float* sy = sh + NPTS;
    float* sz = sh + 2*NPTS;
    __shared__ float    wv[2][32];
    __shared__ unsigned wi[2][32];

    const int b = blockIdx.x, t = threadIdx.x;
    const int lane = t & 31, warp = t >> 5;
    const float* base = xyz + (size_t)b*NPTS*3;

    float px[4], py[4], pz[4], dist[4];
#pragma unroll
    for (int k = 0; k < 4; k++) {
        int p = t + k*1024;
        float x = base[p*3+0], y = base[p*3+1], z = base[p*3+2];
        px[k]=x; py[k]=y; pz[k]=z;
        sx[p]=x; sy[p]=y; sz[p]=z;
        dist[k] = 1e10f;
    }
    __syncthreads();

    int far_ = 0;
    float* o = out_xyz + (size_t)b*SPOINT*3;

    for (int i = 0; i < SPOINT; i++) {
        const int buf = i & 1;
        float cx = sx[far_], cy = sy[far_], cz = sz[far_];
        if (t == 0) { o[i*3+0] = cx; o[i*3+1] = cy; o[i*3+2] = cz; }

        float bestv = -1.0f; unsigned besti = 0u;
#pragma unroll
        for (int k = 0; k < 4; k++) {
            float dx = px[k]-cx, dy = py[k]-cy, dz = pz[k]-cz;
            float d = __fadd_rn(__fadd_rn(__fmul_rn(dx,dx), __fmul_rn(dy,dy)),
                                __fmul_rn(dz,dz));
            float nd = fminf(dist[k], d);
            dist[k] = nd;
            if (nd > bestv) { bestv = nd; besti = (unsigned)(t + k*1024); }
        }
        unsigned uv = __float_as_uint(bestv);
        unsigned mv = __reduce_max_sync(0xffffffffu, uv);
        unsigned ci = (uv == mv) ? besti : 0xffffffffu;
        unsigned mi = __reduce_min_sync(0xffffffffu, ci);
        if (lane == 0) { wv[buf][warp] = __uint_as_float(mv); wi[buf][warp] = mi; }
        __syncthreads();
        unsigned uv2 = __float_as_uint(wv[buf][lane]);
        unsigned mv2 = __reduce_max_sync(0xffffffffu, uv2);
        unsigned ci2 = (uv2 == mv2) ? wi[buf][lane] : 0xffffffffu;
        far_ = (int)__reduce_min_sync(0xffffffffu, ci2);
    }
}

// =====================================================================
// 2) Ball query (unchanged)
// =====================================================================
__global__ __launch_bounds__(128)
void ballquery_kernel(const float* __restrict__ xyz, const float* __restrict__ newxyz)
{
    const int w    = (blockIdx.x * 128 + threadIdx.x) >> 5;
    const int lane = threadIdx.x & 31;
    const int b = w >> 10, s = w & 1023;

    const float* nx = newxyz + ((size_t)(b*SPOINT + s))*3;
    const float cx = nx[0], cy = nx[1], cz = nx[2];
    const float r2 = 0.04f;
    const float* base = xyz + (size_t)b*NPTS*3;
    int* dst = g_ballidx + (size_t)w*KSAMP;

    int cnt = 0, first = 0;
    for (int b0 = 0; b0 < NPTS; b0 += 32) {
        int p = b0 + lane;
        float dx = cx - base[p*3+0];
        float dy = cy - base[p*3+1];
        float dz = cz - base[p*3+2];
        float d = __fadd_rn(__fadd_rn(__fmul_rn(dx,dx), __fmul_rn(dy,dy)),
                            __fmul_rn(dz,dz));
        bool in = !(d > r2);
        unsigned mask = __ballot_sync(0xffffffffu, in);
        if (cnt == 0 && mask) first = b0 + __ffs(mask) - 1;
        int pos = cnt + __popc(mask & ((1u << lane) - 1u));
        if (in && pos < KSAMP) dst[pos] = p;
        cnt += __popc(mask);
        if (cnt >= KSAMP) break;
    }
    if (cnt < KSAMP && lane < KSAMP - cnt) dst[cnt + lane] = first;
}

// =====================================================================
// GEMM via mma.sync m16n8k16 bf16, 3-term split. 128x64 tiles (g0/g1).
// =====================================================================

// gemm0 smem layout (bytes)
#define G0_WXYZ 0          // 192 floats -> 768
#define G0_SB   768        // 64  floats -> 1024
#define G0_SXYZ 1024       // 128*4 floats -> 3072
#define G0_AHI  3072       // 128*144 = 18432 -> 21504
#define G0_ALO  21504      // -> 39936
#define G0_BHI  39936      // 64*144 = 9216 -> 49152
#define G0_BLO  49152      // -> 58368
#define G0_SM   58368

__global__ __launch_bounds__(128)
void gemm0_kernel(const float* __restrict__ xyz, const float* __restrict__ points,
                  const float* __restrict__ w0, const float* __restrict__ b0,
                  const float* __restrict__ newxyz)
{
    extern __shared__ char smc[];
    float* wxyz = (float*)(smc + G0_WXYZ);
    float* sb   = (float*)(smc + G0_SB);
    float* sxyz = (float*)(smc + G0_SXYZ);
    char* sAhi = smc + G0_AHI;
    char* sAlo = smc + G0_ALO;
    char* sBhi = smc + G0_BHI;
    char* sBlo = smc + G0_BLO;

    const int tid = threadIdx.x;
    const int row0 = blockIdx.x * 128;

    for (int i = tid; i < 192; i += 128) wxyz[i] = w0[(i/3)*CIN + (i%3)];
    if (tid < 64) sb[tid] = b0[tid];

    for (int i = tid; i < 64*64; i += 128) {
        int o = i >> 6, k = i & 63;
        float x = w0[o*CIN + 3 + k];
        __nv_bfloat16 h = __float2bfloat16(x);
        __nv_bfloat16 l = __float2bfloat16(x - __bfloat162float(h));
        *(__nv_bfloat16*)(sBhi + o*ASTRIDE + k*2) = h;
        *(__nv_bfloat16*)(sBlo + o*ASTRIDE + k*2) = l;
    }

    // gather A row (one per thread)
    {
        const int r = tid;
        const int row = row0 + r;
        const int bb = row >> 15;
        const int ss = (row >> 5) & 1023;
        const int idx = g_ballidx[row];
        const float* prow = points + ((size_t)(bb*NPTS + idx))*CFEAT;
        const float* pxyz = xyz + ((size_t)(bb*NPTS + idx))*3;
        const float* nv = newxyz + ((size_t)(bb*SPOINT + ss))*3;
        float nx0 = (pxyz[0]-nv[0]) / 0.2f;
        float nx1 = (pxyz[1]-nv[1]) / 0.2f;
        float nx2 = (pxyz[2]-nv[2]) / 0.2f;
        ((float4*)sxyz)[r] = make_float4(nx0, nx1, nx2, 0.f);
#pragma unroll
        for (int kk = 0; kk < 64; kk += 8) {
            float4 u0 = *(const float4*)&prow[kk];
            float4 u1 = *(const float4*)&prow[kk+4];
            uint32_t whi[4], wlo[4];
            split_pack(u0.x, u0.y, whi[0], wlo[0]);
            split_pack(u0.z, u0.w, whi[1], wlo[1]);
            split_pack(u1.x, u1.y, whi[2], wlo[2]);
            split_pack(u1.z, u1.w, whi[3], wlo[3]);
            *(uint4*)(sAhi + r*ASTRIDE + kk*2) = make_uint4(whi[0],whi[1],whi[2],whi[3]);
            *(uint4*)(sAlo + r*ASTRIDE + kk*2) = make_uint4(wlo[0],wlo[1],wlo[2],wlo[3]);
        }
    }
    __syncthreads();

    const int lane = tid & 31, w = tid >> 5;
    const uint32_t aHi = smem_u32(sAhi), aLo = smem_u32(sAlo);
    const uint32_t bHi = smem_u32(sBhi), bLo = smem_u32(sBlo);
    const int aRow = w*32 + (lane & 15);
    const int aCol = (lane >> 4) * 8;
    const int bN   = (lane & 7) + ((lane & 16) ? 8 : 0);
    const int bK   = (lane & 8) ? 8 : 0;

    float acc[2][8][4];
#pragma unroll
    for (int i=0;i<2;i++)
#pragma unroll
        for (int j=0;j<8;j++)
#pragma unroll
            for (int q=0;q<4;q++) acc[i][j][q]=0.f;

#pragma unroll
    for (int kk = 0; kk < 64; kk += 16) {
        uint32_t ahi[2][4], alo[2][4];
#pragma unroll
        for (int mt = 0; mt < 2; mt++) {
            ldsm_x4(ahi[mt], aHi + (aRow + mt*16)*ASTRIDE + (kk + aCol)*2);
            ldsm_x4(alo[mt], aLo + (aRow + mt*16)*ASTRIDE + (kk + aCol)*2);
        }
        uint32_t bhi[4][4], blo[4][4];
#pragma unroll
        for (int p = 0; p < 4; p++) {
            ldsm_x4(bhi[p], bHi + (p*16 + bN)*ASTRIDE + (kk + bK)*2);
            ldsm_x4(blo[p], bLo + (p*16 + bN)*ASTRIDE + (kk + bK)*2);
        }
#pragma unroll
        for (int mt = 0; mt < 2; mt++)
#pragma unroll
            for (int nt = 0; nt < 8; nt++) {
                const uint32_t* bh = &bhi[nt>>1][(nt&1)*2];
                const uint32_t* bl = &blo[nt>>1][(nt&1)*2];
                mma16816(acc[mt][nt], ahi[mt], bh);
                mma16816(acc[mt][nt], ahi[mt], bl);
                mma16816(acc[mt][nt], alo[mt], bh);
            }
    }

    // epilogue: + bias + fp32 xyz correction
    const int qr = lane >> 2;
    const int qc = (lane & 3) * 2;
#pragma unroll
    for (int mt = 0; mt < 2; mt++) {
        int rl = w*32 + mt*16 + qr;
        float4 sx0 = ((float4*)sxyz)[rl];
        float4 sx1 = ((float4*)sxyz)[rl + 8];
        size_t rbase = (size_t)(row0 + rl);
#pragma unroll
        for (int nt = 0; nt < 8; nt++) {
            int c0 = nt*8 + qc, c1 = c0 + 1;
            float w00 = wxyz[c0*3+0], w01 = wxyz[c0*3+1], w02 = wxyz[c0*3+2];
            float w10 = wxyz[c1*3+0], w11 = wxyz[c1*3+1], w12 = wxyz[c1*3+2];
            float v00 = acc[mt][nt][0] + sb[c0] + sx0.x*w00 + sx0.y*w01 + sx0.z*w02;
            float v01 = acc[mt][nt][1] + sb[c1] + sx0.x*w10 + sx0.y*w11 + sx0.z*w12;
            float v10 = acc[mt][nt][2] + sb[c0] + sx1.x*w00 + sx1.y*w01 + sx1.z*w02;
            float v11 = acc[mt][nt][3] + sb[c1] + sx1.x*w10 + sx1.y*w11 + sx1.z*w12;
            *(float2*)&g_h0[rbase*64 + c0]     = make_float2(v00, v01);
            *(float2*)&g_h0[(rbase+8)*64 + c0] = make_float2(v10, v11);
        }
    }
}

// gemm1 smem layout
#define G1_SA   0
#define G1_SS   256
#define G1_SB   512
#define G1_AHI  1024
#define G1_ALO  19456
#define G1_BHI  37888
#define G1_BLO  47104
#define G1_SM   56320

__global__ __launch_bounds__(128)
void gemm1_kernel(const float* __restrict__ wm, const float* __restrict__ bbias)
{
    extern __shared__ char smc[];
    float* sa  = (float*)(smc + G1_SA);
    float* ssh = (float*)(smc + G1_SS);
    float* sb  = (float*)(smc + G1_SB);
    char* sAhi = smc + G1_AHI;
    char* sAlo = smc + G1_ALO;
    char* sBhi = smc + G1_BHI;
    char* sBlo = smc + G1_BLO;

    const int tid = threadIdx.x;
    const int row0 = blockIdx.x * 128;

    if (tid < 64) { sa[tid] = g_scale[0][tid]; ssh[tid] = g_shift[0][tid]; sb[tid] = bbias[tid]; }

    for (int i = tid; i < 64*64; i += 128) {
        int o = i >> 6, k = i & 63;
        float x = wm[i];
        __nv_bfloat16 h = __float2bfloat16(x);
        __nv_bfloat16 l = __float2bfloat16(x - __bfloat162float(h));
        *(__nv_bfloat16*)(sBhi + o*ASTRIDE + k*2) = h;
        *(__nv_bfloat16*)(sBlo + o*ASTRIDE + k*2) = l;
    }
    __syncthreads();   // sa/ssh visible

    {
        const int r = tid;
        const float* hrow = &g_h0[(size_t)(row0 + r)*64];
#pragma unroll
        for (int kk = 0; kk < 64; kk += 8) {
            float4 u0 = *(const float4*)&hrow[kk];
            float4 u1 = *(const float4*)&hrow[kk+4];
            float v[8] = {u0.x,u0.y,u0.z,u0.w,u1.x,u1.y,u1.z,u1.w};
#pragma unroll
            for (int j = 0; j < 8; j++) v[j] = fmaxf(0.f, fmaf(sa[kk+j], v[j], ssh[kk+j]));
            uint32_t whi[4], wlo[4];
#pragma unroll
            for (int j = 0; j < 4; j++) split_pack(v[2*j], v[2*j+1], whi[j], wlo[j]);
            *(uint4*)(sAhi + r*ASTRIDE + kk*2) = make_uint4(whi[0],whi[1],whi[2],whi[3]);
            *(uint4*)(sAlo + r*ASTRIDE + kk*2) = make_uint4(wlo[0],wlo[1],wlo[2],wlo[3]);
        }
    }
    __syncthreads();

    const int lane = tid & 31, w = tid >> 5;
    const uint32_t aHi = smem_u32(sAhi), aLo = smem_u32(sAlo);
    const uint32_t bHi = smem_u32(sBhi), bLo = smem_u32(sBlo);
    const int aRow = w*32 + (lane & 15);
    const int aCol = (lane >> 4) * 8;
    const int bN   = (lane & 7) + ((lane & 16) ? 8 : 0);
    const int bK   = (lane & 8) ? 8 : 0;

    float acc[2][8][4];
#pragma unroll
    for (int i=0;i<2;i++)
#pragma unroll
        for (int j=0;j<8;j++)
#pragma unroll
            for (int q=0;q<4;q++) acc[i][j][q]=0.f;

#pragma unroll
    for (int kk = 0; kk < 64; kk += 16) {
        uint32_t ahi[2][4], alo[2][4];
#pragma unroll
        for (int mt = 0; mt < 2; mt++) {
            ldsm_x4(ahi[mt], aHi + (aRow + mt*16)*ASTRIDE + (kk + aCol)*2);
            ldsm_x4(alo[mt], aLo + (aRow + mt*16)*ASTRIDE + (kk + aCol)*2);
        }
        uint32_t bhi[4][4], blo[4][4];
#pragma unroll
        for (int p = 0; p < 4; p++) {
            ldsm_x4(bhi[p], bHi + (p*16 + bN)*ASTRIDE + (kk + bK)*2);
            ldsm_x4(blo[p], bLo + (p*16 + bN)*ASTRIDE + (kk + bK)*2);
        }
#pragma unroll
        for (int mt = 0; mt < 2; mt++)
#pragma unroll
            for (int nt = 0; nt < 8; nt++) {
                const uint32_t* bh = &bhi[nt>>1][(nt&1)*2];
                const uint32_t* bl = &blo[nt>>1][(nt&1)*2];
                mma16816(acc[mt][nt], ahi[mt], bh);
                mma16816(acc[mt][nt], ahi[mt], bl);
                mma16816(acc[mt][nt], alo[mt], bh);
            }
    }

    const int qr = lane >> 2;
    const int qc = (lane & 3) * 2;
#pragma unroll
    for (int mt = 0; mt < 2; mt++) {
        size_t rbase = (size_t)(row0 + w*32 + mt*16 + qr);
#pragma unroll
        for (int nt = 0; nt < 8; nt++) {
            int c0 = nt*8 + qc, c1 = c0 + 1;
            *(float2*)&g_h1[rbase*64 + c0]     = make_float2(acc[mt][nt][0] + sb[c0], acc[mt][nt][1] + sb[c1]);
            *(float2*)&g_h1[(rbase+8)*64 + c0] = make_float2(acc[mt][nt][2] + sb[c0], acc[mt][nt][3] + sb[c1]);
        }
    }
}

// gemm2 smem layout (256 threads, N=128)
#define G2_SA    0
#define G2_SS    256
#define G2_SB    512      // 128 floats -> 1024
#define G2_AHI   1024     // -> 19456
#define G2_ALO   19456    // -> 37888
#define G2_BHI   37888    // 128*144=18432 -> 56320
#define G2_BLO   56320    // -> 74752
#define G2_STAGE 1024     // overlaps A/B after mainloop: 128*130*4 = 66560 -> 67584
#define G2_PS    67584    // 2*128 floats -> 68608
#define G2_PQ    68608    // 2*128 floats -> 69632
#define G2_SM    74752

__global__ __launch_bounds__(256)
void gemm2_kernel(const float* __restrict__ wm, const float* __restrict__ bbias)
{
    extern __shared__ char smc[];
    float* sa  = (float*)(smc + G2_SA);
    float* ssh = (float*)(smc + G2_SS);
    float* sb  = (float*)(smc + G2_SB);
    char* sAhi = smc + G2_AHI;
    char* sAlo = smc + G2_ALO;
    char* sBhi = smc + G2_BHI;
    char* sBlo = smc + G2_BLO;

    const int tid = threadIdx.x;
    const int row0 = blockIdx.x * 128;

    if (tid < 64)  { sa[tid] = g_scale[1][tid]; ssh[tid] = g_shift[1][tid]; }
    if (tid < 128) sb[tid] = bbias[tid];

    for (int i = tid; i < 128*64; i += 256) {
        int o = i >> 6, k = i & 63;
        float x = wm[i];
        __nv_bfloat16 h = __float2bfloat16(x);
        __nv_bfloat16 l = __float2bfloat16(x - __bfloat162float(h));
        *(__nv_bfloat16*)(sBhi + o*ASTRIDE + k*2) = h;
        *(__nv_bfloat16*)(sBlo + o*ASTRIDE + k*2) = l;
    }
    __syncthreads();

    {
        const int r = tid >> 1;
        const int kbase = (tid & 1) * 32;
        const float* hrow = &g_h1[(size_t)(row0 + r)*64];
#pragma unroll
        for (int kk = kbase; kk < kbase + 32; kk += 8) {
            float4 u0 = *(const float4*)&hrow[kk];
            float4 u1 = *(const float4*)&hrow[kk+4];
            float v[8] = {u0.x,u0.y,u0.z,u0.w,u1.x,u1.y,u1.z,u1.w};
#pragma unroll
            for (int j = 0; j < 8; j++) v[j] = fmaxf(0.f, fmaf(sa[kk+j], v[j], ssh[kk+j]));
            uint32_t whi[4], wlo[4];
#pragma unroll
            for (int j = 0; j < 4; j++) split_pack(v[2*j], v[2*j+1], whi[j], wlo[j]);
            *(uint4*)(sAhi + r*ASTRIDE + kk*2) = make_uint4(whi[0],whi[1],whi[2],whi[3]);
            *(uint4*)(sAlo + r*ASTRIDE + kk*2) = make_uint4(wlo[0],wlo[1],wlo[2],wlo[3]);
        }
    }
    __syncthreads();

    const int lane = tid & 31, w = tid >> 5;   // 8 warps, warp = 16 rows
    const uint32_t aHi = smem_u32(sAhi), aLo = smem_u32(sAlo);
    const uint32_t bHi = smem_u32(sBhi), bLo = smem_u32(sBlo);
    const int aRow = w*16 + (lane & 15);
    const int aCol = (lane >> 4) * 8;
    const int bN   = (lane & 7) + ((lane & 16) ? 8 : 0);
    const int bK   = (lane & 8) ? 8 : 0;

    float acc[16][4];
#pragma unroll
    for (int j=0;j<16;j++)
#pragma unroll
        for (int q=0;q<4;q++) acc[j][q]=0.f;

#pragma unroll
    for (int kk = 0; kk < 64; kk += 16) {
        uint32_t ahi[4], alo[4];
        ldsm_x4(ahi, aHi + aRow*ASTRIDE + (kk + aCol)*2);
        ldsm_x4(alo, aLo + aRow*ASTRIDE + (kk + aCol)*2);
        uint32_t bhi[8][4], blo[8][4];
#pragma unroll
        for (int p = 0; p < 8; p++) {
            ldsm_x4(bhi[p], bHi + (p*16 + bN)*ASTRIDE + (kk + bK)*2);
            ldsm_x4(blo[p], bLo + (p*16 + bN)*ASTRIDE + (kk + bK)*2);
        }
#pragma unroll
        for (int nt = 0; nt < 16; nt++) {
            const uint32_t* bh = &bhi[nt>>1][(nt&1)*2];
            const uint32_t* bl = &blo[nt>>1][(nt&1)*2];
            mma16816(acc[nt], ahi, bh);
            mma16816(acc[nt], ahi, bl);
            mma16816(acc[nt], alo, bh);
        }
    }
    __syncthreads();     // A/B planes dead; stage overlaps them

    // stage D into smem [128][130] (even stride -> float2-aligned)
    float* stage = (float*)(smc + G2_STAGE);
    {
        const int qr = lane >> 2;
        const int qc = (lane & 3) * 2;
        int r0 = w*16 + qr;
#pragma unroll
        for (int nt = 0; nt < 16; nt++) {
            int c0 = nt*8 + qc;
            *(float2*)&stage[r0*130 + c0]      = make_float2(acc[nt][0], acc[nt][1]);
            *(float2*)&stage[(r0+8)*130 + c0]  = make_float2(acc[nt][2], acc[nt][3]);
        }
    }
    __syncthreads();

    // reductions: c = tid&127, half = tid>>7 covers rows half*64..+63
    {
        float* ps = (float*)(smc + G2_PS);
        float* pq = (float*)(smc + G2_PQ);
        const int c = tid & 127;
        const int half = tid >> 7;
        const float bc = sb[c];
        float s = 0.f, q = 0.f;
        float mx[2] = {-3.4e38f, -3.4e38f}, mn[2] = {3.4e38f, 3.4e38f};
#pragma unroll 4
        for (int rr = 0; rr < 64; rr++) {
            float v = stage[(half*64 + rr)*130 + c] + bc;
            s += v; q = fmaf(v, v, q);
            int g = rr >> 5;
            mx[g] = fmaxf(mx[g], v); mn[g] = fminf(mn[g], v);
        }
        ps[half*128 + c] = s;
        pq[half*128 + c] = q;
#pragma unroll
        for (int g = 0; g < 2; g++) {
            size_t grp = (size_t)blockIdx.x*4 + half*2 + g;
            g_gmax[grp*128 + c] = mx[g];
            g_gmin[grp*128 + c] = mn[g];
        }
        __syncthreads();
        if (tid < 128) {
            g_psum[blockIdx.x*128 + tid] = ps[tid] + ps[128 + tid];
            g_psq [blockIdx.x*128 + tid] = pq[tid] + pq[128 + tid];
        }
    }
}

// =====================================================================
// partials: per-block (128 rows) per-channel sum/sumsq over h (64 ch)
// =====================================================================
__global__ __launch_bounds__(256)
void partials_kernel(int which)
{
    __shared__ float ps[4][64], pq[4][64];
    const float* h = which ? g_h1 : g_h0;
    const int c = threadIdx.x & 63;
    const int rq = threadIdx.x >> 6;
    const size_t base = (size_t)blockIdx.x*128 + rq*32;

    float s = 0.f, q = 0.f;
#pragma unroll 4
    for (int r = 0; r < 32; r++) {
        float v = h[(base + r)*64 + c];
        s += v; q = fmaf(v, v, q);
    }
    ps[rq][c] = s; pq[rq][c] = q;
    __syncthreads();
    if (threadIdx.x < 64) {
        g_psum[blockIdx.x*64 + c] = ps[0][c] + ps[1][c] + ps[2][c] + ps[3][c];
        g_psq [blockIdx.x*64 + c] = pq[0][c] + pq[1][c] + pq[2][c] + pq[3][c];
    }
}

// =====================================================================
// fold: BN -> per-channel affine (a, c)
// =====================================================================
__global__ __launch_bounds__(256)
void fold_kernel(const float* __restrict__ g, const float* __restrict__ be,
                 int layer, int nch)
{
    __shared__ double ssum[256], ssq[256];
    const int ch = blockIdx.x;
    const int t  = threadIdx.x;

    double s = 0.0, q = 0.0;
    for (int b = t; b < NBLK; b += 256) {
        s += (double)g_psum[b*nch + ch];
        q += (double)g_psq [b*nch + ch];
    }
    ssum[t] = s; ssq[t] = q;
    __syncthreads();
#pragma unroll
    for (int off = 128; off > 0; off >>= 1) {
        if (t < off) { ssum[t] += ssum[t+off]; ssq[t] += ssq[t+off]; }
        __syncthreads();
    }
    if (t == 0) {
        const double M = (double)MROWS;
        double mu  = ssum[0] / M;
        double var = ssq[0] / M - mu*mu;
        float rs = (float)(1.0 / sqrt(var + 1e-5));
        float a  = g[ch] * rs;
        float c  = be[ch] - (float)mu * a;
        g_scale[layer][ch] = a;
        g_shift[layer][ch] = c;
    }
}

// =====================================================================
// Final: relu(a * (a>=0 ? gmax : gmin) + c)
// =====================================================================
__global__ void final_kernel(float* __restrict__ out)
{
    int grp = blockIdx.x, ch = threadIdx.x;
    float a = g_scale[2][ch], c = g_shift[2][ch];
    float h = (a >= 0.f) ? g_gmax[(size_t)grp*128 + ch] : g_gmin[(size_t)grp*128 + ch];
    out[OUT_XYZ_ELEMS + (size_t)grp*128 + ch] = fmaxf(0.f, fmaf(a, h, c));
}

// =====================================================================
extern "C" void kernel_launch(void* const* d_in, const int* in_sizes, int n_in,
                              void* d_out, int out_size)
{
    const float* xyz    = (const float*)d_in[0];
    const float* points = (const float*)d_in[1];
    const float* w0  = (const float*)d_in[2];
    const float* b0  = (const float*)d_in[3];
    const float* g0  = (const float*)d_in[4];
    const float* be0 = (const float*)d_in[5];
    const float* w1  = (const float*)d_in[6];
    const float* b1  = (const float*)d_in[7];
    const float* g1  = (const float*)d_in[8];
    const float* be1 = (const float*)d_in[9];
    const float* w2  = (const float*)d_in[10];
    const float* b2  = (const float*)d_in[11];
    const float* g2  = (const float*)d_in[12];
    const float* be2 = (const float*)d_in[13];
    float* out = (float*)d_out;

    const int FPS_SM = NPTS*3*4;             // 49152
    cudaFuncSetAttribute(fps_kernel,   cudaFuncAttributeMaxDynamicSharedMemorySize, FPS_SM);
    cudaFuncSetAttribute(gemm0_kernel, cudaFuncAttributeMaxDynamicSharedMemorySize, G0_SM);
    cudaFuncSetAttribute(gemm1_kernel, cudaFuncAttributeMaxDynamicSharedMemorySize, G1_SM);
    cudaFuncSetAttribute(gemm2_kernel, cudaFuncAttributeMaxDynamicSharedMemorySize, G2_SM);

    fps_kernel<<<BATCH, 1024, FPS_SM>>>(xyz, out);                  // 0
    ballquery_kernel<<<(NGROUP*32)/128, 128>>>(xyz, out);           // 1
    gemm0_kernel<<<NBLK, 128, G0_SM>>>(xyz, points, w0, b0, out);   // 2
    partials_kernel<<<NBLK, 256>>>(0);                              // 3
    fold_kernel<<<64, 256>>>(g0, be0, 0, 64);                       // 4
    gemm1_kernel<<<NBLK, 128, G1_SM>>>(w1, b1);                     // 5  <- ncu -s 5
    partials_kernel<<<NBLK, 256>>>(1);                              // 6
    fold_kernel<<<64, 256>>>(g1, be1, 1, 64);                       // 7
    gemm2_kernel<<<NBLK, 256, G2_SM>>>(w2, b2);                     // 8
    fold_kernel<<<128, 256>>>(g2, be2, 2, 128);                     // 9
    final_kernel<<<NGROUP, 128>>>(out);                             // 10
}

// round 11
// speedup vs baseline: 5.6142x; 1.0404x over previous
#include <cuda_runtime.h>
#include <cuda_bf16.h>
#include <cstdint>
#include <math.h>

// ---------------- problem constants ----------------
#define BATCH    16
#define NPTS     4096
#define CFEAT    64
#define SPOINT   1024
#define KSAMP    32
#define CIN      67
#define MROWS    (BATCH*SPOINT*KSAMP)      // 524288
#define NGROUP   (BATCH*SPOINT)            // 16384
#define NBLK     (MROWS/128)               // 4096
#define OUT_XYZ_ELEMS (BATCH*SPOINT*3)     // 49152
#define ASTRIDE  144                        // bytes per padded bf16 row (72 halves)

// ---------------- device scratch ----------------
__device__ int   g_ballidx[MROWS];
__device__ float g_h0[(size_t)MROWS*64];
__device__ float g_h1[(size_t)MROWS*64];
__device__ float g_gmax[(size_t)NGROUP*128];
__device__ float g_gmin[(size_t)NGROUP*128];
__device__ float g_psum[NBLK*128];
__device__ float g_psq [NBLK*128];
__device__ float g_scale[3][128];
__device__ float g_shift[3][128];
__device__ __nv_bfloat16 g_whi[3][128*72];   // pre-split weight hi planes (ASTRIDE layout)
__device__ __nv_bfloat16 g_wlo[3][128*72];   // lo planes

// ---------------- helpers ----------------
__device__ __forceinline__ uint32_t smem_u32(const void* p) {
    uint32_t a;
    asm("{ .reg .u64 t; cvta.to.shared.u64 t, %1; cvt.u32.u64 %0, t; }" : "=r"(a) : "l"(p));
    return a;
}
__device__ __forceinline__ void ldsm_x4(uint32_t* r, uint32_t addr) {
    asm volatile("ldmatrix.sync.aligned.m8n8.x4.shared.b16 {%0,%1,%2,%3}, [%4];"
                 : "=r"(r[0]), "=r"(r[1]), "=r"(r[2]), "=r"(r[3]) : "r"(addr));
}
__device__ __forceinline__ void mma16816(float* d, const uint32_t* a, const uint32_t* b) {
    asm volatile(
        "mma.sync.aligned.m16n8k16.row.col.f32.bf16.bf16.f32 "
        "{%0,%1,%2,%3}, {%4,%5,%6,%7}, {%8,%9}, {%0,%1,%2,%3};"
        : "+f"(d[0]), "+f"(d[1]), "+f"(d[2]), "+f"(d[3])
        : "r"(a[0]), "r"(a[1]), "r"(a[2]), "r"(a[3]), "r"(b[0]), "r"(b[1]));
}
__device__ __forceinline__ void split_pack(float a0, float a1, uint32_t& whi, uint32_t& wlo) {
    __nv_bfloat16 h0 = __float2bfloat16(a0), h1 = __float2bfloat16(a1);
    float r0 = a0 - __bfloat162float(h0), r1 = a1 - __bfloat162float(h1);
    __nv_bfloat16 l0 = __float2bfloat16(r0), l1 = __float2bfloat16(r1);
    whi = ((uint32_t)__bfloat16_as_ushort(h1) << 16) | __bfloat16_as_ushort(h0);
    wlo = ((uint32_t)__bfloat16_as_ushort(l1) << 16) | __bfloat16_as_ushort(l0);
}

// =====================================================================
// 0) prep: split weights into bf16 hi/lo planes (ASTRIDE-padded rows)
// =====================================================================
__global__ __launch_bounds__(256)
void prep_kernel(const float* __restrict__ w0, const float* __restrict__ w1,
                 const float* __restrict__ w2)
{
    int i = blockIdx.x*256 + threadIdx.x;   // 16384 total
    int layer, o, k; float x;
    if (i < 4096)      { layer = 0; o = i >> 6;            k = i & 63; x = w0[o*CIN + 3 + k]; }
    else if (i < 8192) { layer = 1; int j = i - 4096; o = j >> 6; k = j & 63; x = w1[j]; }
    else               { layer = 2; int j = i - 8192; o = j >> 6; k = j & 63; x = w2[j]; }
    __nv_bfloat16 h = __float2bfloat16(x);
    __nv_bfloat16 l = __float2bfloat16(x - __bfloat162float(h));
    g_whi[layer][o*72 + k] = h;
    g_wlo[layer][o*72 + k] = l;
}

// =====================================================================
// 1) FPS: contiguous ownership (thread t owns 4t..4t+3).
//    Lowest-index tie-break via redux_max + ballot + ffs (index order
//    equals lane/warp order). One barrier per step (double buffer).
// =====================================================================
__global__ void fps_kernel(const float* __restrict__ xyz, float* __restrict__ out_xyz)
{
    extern __shared__ float sh[];
    float* sx = sh;
    float* sy = sh + NPTS;
    float* sz = sh + 2*NPTS;
    __shared__ float    wv[2][32];
    __shared__ unsigned wi[2][32];

    const int b = blockIdx.x, t = threadIdx.x;
    const int lane = t & 31, warp = t >> 5;
    const float* base = xyz + (size_t)b*NPTS*3;

    float px[4], py[4], pz[4], dist[4];
    {
        const float4* b4 = (const float4*)base;
        float4 f0 = b4[3*t], f1 = b4[3*t+1], f2 = b4[3*t+2];
        px[0]=f0.x; py[0]=f0.y; pz[0]=f0.z;
        px[1]=f0.w; py[1]=f1.x; pz[1]=f1.y;
        px[2]=f1.z; py[2]=f1.w; pz[2]=f2.x;
        px[3]=f2.y; py[3]=f2.z; pz[3]=f2.w;
#pragma unroll
        for (int k = 0; k < 4; k++) {
            int p = 4*t + k;
            sx[p]=px[k]; sy[p]=py[k]; sz[p]=pz[k];
            dist[k] = 1e10f;
        }
    }
    __syncthreads();

    int far_ = 0;
    float* o = out_xyz + (size_t)b*SPOINT*3;

    for (int i = 0; i < SPOINT; i++) {
        const int buf = i & 1;
        float cx = sx[far_], cy = sy[far_], cz = sz[far_];
        if (t == 0) { o[i*3+0] = cx; o[i*3+1] = cy; o[i*3+2] = cz; }

        float bestv = -1.0f; unsigned besti = 0u;
#pragma unroll
        for (int k = 0; k < 4; k++) {
            float dx = px[k]-cx, dy = py[k]-cy, dz = pz[k]-cz;
            float d = __fadd_rn(__fadd_rn(__fmul_rn(dx,dx), __fmul_rn(dy,dy)),
                                __fmul_rn(dz,dz));
            float nd = fminf(dist[k], d);
            dist[k] = nd;
            if (nd > bestv) { bestv = nd; besti = (unsigned)(4*t + k); }
        }
        unsigned uv = __float_as_uint(bestv);
        unsigned mv = __reduce_max_sync(0xffffffffu, uv);
        unsigned msk = __ballot_sync(0xffffffffu, uv == mv);
        unsigned bi = __shfl_sync(0xffffffffu, besti, __ffs(msk) - 1);
        if (lane == 0) { wv[buf][warp] = __uint_as_float(mv); wi[buf][warp] = bi; }
        __syncthreads();
        unsigned uv2 = __float_as_uint(wv[buf][lane]);
        unsigned mv2 = __reduce_max_sync(0xffffffffu, uv2);
        unsigned msk2 = __ballot_sync(0xffffffffu, uv2 == mv2);
        far_ = (int)wi[buf][__ffs(msk2) - 1];
    }
}

// =====================================================================
// 2) Ball query (unchanged)
// =====================================================================
__global__ __launch_bounds__(128)
void ballquery_kernel(const float* __restrict__ xyz, const float* __restrict__ newxyz)
{
    const int w    = (blockIdx.x * 128 + threadIdx.x) >> 5;
    const int lane = threadIdx.x & 31;
    const int b = w >> 10, s = w & 1023;

    const float* nx = newxyz + ((size_t)(b*SPOINT + s))*3;
    const float cx = nx[0], cy = nx[1], cz = nx[2];
    const float r2 = 0.04f;
    const float* base = xyz + (size_t)b*NPTS*3;
    int* dst = g_ballidx + (size_t)w*KSAMP;

    int cnt = 0, first = 0;
    for (int b0 = 0; b0 < NPTS; b0 += 32) {
        int p = b0 + lane;
        float dx = cx - base[p*3+0];
        float dy = cy - base[p*3+1];
        float dz = cz - base[p*3+2];
        float d = __fadd_rn(__fadd_rn(__fmul_rn(dx,dx), __fmul_rn(dy,dy)),
                            __fmul_rn(dz,dz));
        bool in = !(d > r2);
        unsigned mask = __ballot_sync(0xffffffffu, in);
        if (cnt == 0 && mask) first = b0 + __ffs(mask) - 1;
        int pos = cnt + __popc(mask & ((1u << lane) - 1u));
        if (in && pos < KSAMP) dst[pos] = p;
        cnt += __popc(mask);
        if (cnt >= KSAMP) break;
    }
    if (cnt < KSAMP && lane < KSAMP - cnt) dst[cnt + lane] = first;
}

// =====================================================================
// GEMM via mma.sync m16n8k16 bf16, 3-term split.
// =====================================================================

// gemm0 smem layout (bytes)
#define G0_WXYZ 0          // 192 floats -> 768
#define G0_SB   768        // 64  floats -> 1024
#define G0_SXYZ 1024       // 128*4 floats -> 3072
#define G0_AHI  3072       // 128*144 = 18432 -> 21504
#define G0_ALO  21504      // -> 39936
#define G0_BHI  39936      // 64*144 = 9216 -> 49152
#define G0_BLO  49152      // -> 58368
#define G0_SM   58368

__global__ __launch_bounds__(128)
void gemm0_kernel(const float* __restrict__ xyz, const float* __restrict__ points,
                  const float* __restrict__ w0, const float* __restrict__ b0,
                  const float* __restrict__ newxyz)
{
    extern __shared__ char smc[];
    float* wxyz = (float*)(smc + G0_WXYZ);
    float* sb   = (float*)(smc + G0_SB);
    float* sxyz = (float*)(smc + G0_SXYZ);
    char* sAhi = smc + G0_AHI;
    char* sAlo = smc + G0_ALO;
    char* sBhi = smc + G0_BHI;
    char* sBlo = smc + G0_BLO;

    const int tid = threadIdx.x;
    const int row0 = blockIdx.x * 128;

    for (int i = tid; i < 192; i += 128) wxyz[i] = w0[(i/3)*CIN + (i%3)];
    if (tid < 64) sb[tid] = b0[tid];

    // copy pre-split B planes (64 rows x 144B each)
    {
        const uint4* shi = (const uint4*)g_whi[0];
        const uint4* slo = (const uint4*)g_wlo[0];
        uint4* dhi = (uint4*)sBhi;
        uint4* dlo = (uint4*)sBlo;
#pragma unroll
        for (int i = 0; i < 576; i += 128) {   // 576 = 64*144/16
            dhi[i + tid&0 ? 0 : i + tid] = shi[i + tid];   // (kept simple below)
        }
    }
    // (re-do cleanly)
    {
        const uint4* shi = (const uint4*)g_whi[0];
        const uint4* slo = (const uint4*)g_wlo[0];
        uint4* dhi = (uint4*)sBhi;
        uint4* dlo = (uint4*)sBlo;
        for (int i = tid; i < 576; i += 128) { dhi[i] = shi[i]; dlo[i] = slo[i]; }
    }

    // gather A row (one per thread)
    {
        const int r = tid;
        const int row = row0 + r;
        const int bb = row >> 15;
        const int ss = (row >> 5) & 1023;
        const int idx = g_ballidx[row];
        const float* prow = points + ((size_t)(bb*NPTS + idx))*CFEAT;
        const float* pxyz = xyz + ((size_t)(bb*NPTS + idx))*3;
        const float* nv = newxyz + ((size_t)(bb*SPOINT + ss))*3;
        float nx0 = (pxyz[0]-nv[0]) / 0.2f;
        float nx1 = (pxyz[1]-nv[1]) / 0.2f;
        float nx2 = (pxyz[2]-nv[2]) / 0.2f;
        ((float4*)sxyz)[r] = make_float4(nx0, nx1, nx2, 0.f);
#pragma unroll
        for (int kk = 0; kk < 64; kk += 8) {
            float4 u0 = *(const float4*)&prow[kk];
            float4 u1 = *(const float4*)&prow[kk+4];
            uint32_t whi[4], wlo[4];
            split_pack(u0.x, u0.y, whi[0], wlo[0]);
            split_pack(u0.z, u0.w, whi[1], wlo[1]);
            split_pack(u1.x, u1.y, whi[2], wlo[2]);
            split_pack(u1.z, u1.w, whi[3], wlo[3]);
            *(uint4*)(sAhi + r*ASTRIDE + kk*2) = make_uint4(whi[0],whi[1],whi[2],whi[3]);
            *(uint4*)(sAlo + r*ASTRIDE + kk*2) = make_uint4(wlo[0],wlo[1],wlo[2],wlo[3]);
        }
    }
    __syncthreads();

    const int lane = tid & 31, w = tid >> 5;
    const uint32_t aHi = smem_u32(sAhi), aLo = smem_u32(sAlo);
    const uint32_t bHi = smem_u32(sBhi), bLo = smem_u32(sBlo);
    const int aRow = w*32 + (lane & 15);
    const int aCol = (lane >> 4) * 8;
    const int bN   = (lane & 7) + ((lane & 16) ? 8 : 0);
    const int bK   = (lane & 8) ? 8 : 0;

    float acc[2][8][4];
#pragma unroll
    for (int i=0;i<2;i++)
#pragma unroll
        for (int j=0;j<8;j++)
#pragma unroll
            for (int q=0;q<4;q++) acc[i][j][q]=0.f;

#pragma unroll
    for (int kk = 0; kk < 64; kk += 16) {
        uint32_t ahi[2][4], alo[2][4];
#pragma unroll
        for (int mt = 0; mt < 2; mt++) {
            ldsm_x4(ahi[mt], aHi + (aRow + mt*16)*ASTRIDE + (kk + aCol)*2);
            ldsm_x4(alo[mt], aLo + (aRow + mt*16)*ASTRIDE + (kk + aCol)*2);
        }
        uint32_t bhi[4][4], blo[4][4];
#pragma unroll
        for (int p = 0; p < 4; p++) {
            ldsm_x4(bhi[p], bHi + (p*16 + bN)*ASTRIDE + (kk + bK)*2);
            ldsm_x4(blo[p], bLo + (p*16 + bN)*ASTRIDE + (kk + bK)*2);
        }
#pragma unroll
        for (int mt = 0; mt < 2; mt++)
#pragma unroll
            for (int nt = 0; nt < 8; nt++) {
                const uint32_t* bh = &bhi[nt>>1][(nt&1)*2];
                const uint32_t* bl = &blo[nt>>1][(nt&1)*2];
                mma16816(acc[mt][nt], ahi[mt], bh);
                mma16816(acc[mt][nt], ahi[mt], bl);
                mma16816(acc[mt][nt], alo[mt], bh);
            }
    }

    // epilogue: + bias + fp32 xyz correction
    const int qr = lane >> 2;
    const int qc = (lane & 3) * 2;
#pragma unroll
    for (int mt = 0; mt < 2; mt++) {
        int rl = w*32 + mt*16 + qr;
        float4 sx0 = ((float4*)sxyz)[rl];
        float4 sx1 = ((float4*)sxyz)[rl + 8];
        size_t rbase = (size_t)(row0 + rl);
#pragma unroll
        for (int nt = 0; nt < 8; nt++) {
            int c0 = nt*8 + qc, c1 = c0 + 1;
            float w00 = wxyz[c0*3+0], w01 = wxyz[c0*3+1], w02 = wxyz[c0*3+2];
            float w10 = wxyz[c1*3+0], w11 = wxyz[c1*3+1], w12 = wxyz[c1*3+2];
            float v00 = acc[mt][nt][0] + sb[c0] + sx0.x*w00 + sx0.y*w01 + sx0.z*w02;
            float v01 = acc[mt][nt][1] + sb[c1] + sx0.x*w10 + sx0.y*w11 + sx0.z*w12;
            float v10 = acc[mt][nt][2] + sb[c0] + sx1.x*w00 + sx1.y*w01 + sx1.z*w02;
            float v11 = acc[mt][nt][3] + sb[c1] + sx1.x*w10 + sx1.y*w11 + sx1.z*w12;
            *(float2*)&g_h0[rbase*64 + c0]     = make_float2(v00, v01);
            *(float2*)&g_h0[(rbase+8)*64 + c0] = make_float2(v10, v11);
        }
    }

    // fused partials over L2-hot h0 tile (A planes dead -> reuse as ps/pq)
    __syncthreads();
    {
        float* ps = (float*)(smc + G0_AHI);          // [8][64]
        float* pq = ps + 512;
        const int c4 = (tid & 15) * 4, rg = tid >> 4;
        float s[4] = {0,0,0,0}, q[4] = {0,0,0,0};
#pragma unroll 4
        for (int k = 0; k < 16; k++) {
            float4 v = *(const float4*)&g_h0[(size_t)(row0 + rg + k*8)*64 + c4];
            s[0]+=v.x; q[0]=fmaf(v.x,v.x,q[0]);
            s[1]+=v.y; q[1]=fmaf(v.y,v.y,q[1]);
            s[2]+=v.z; q[2]=fmaf(v.z,v.z,q[2]);
            s[3]+=v.w; q[3]=fmaf(v.w,v.w,q[3]);
        }
#pragma unroll
        for (int j = 0; j < 4; j++) { ps[rg*64 + c4 + j] = s[j]; pq[rg*64 + c4 + j] = q[j]; }
        __syncthreads();
        if (tid < 64) {
            float ts = 0.f, tq = 0.f;
#pragma unroll
            for (int g = 0; g < 8; g++) { ts += ps[g*64 + tid]; tq += pq[g*64 + tid]; }
            g_psum[blockIdx.x*64 + tid] = ts;
            g_psq [blockIdx.x*64 + tid] = tq;
        }
    }
}

// gemm1 smem layout
#define G1_SA   0
#define G1_SS   256
#define G1_SB   512
#define G1_AHI  1024
#define G1_ALO  19456
#define G1_BHI  37888
#define G1_BLO  47104
#define G1_SM   56320

__global__ __launch_bounds__(128)
void gemm1_kernel(const float* __restrict__ bbias)
{
    extern __shared__ char smc[];
    float* sa  = (float*)(smc + G1_SA);
    float* ssh = (float*)(smc + G1_SS);
    float* sb  = (float*)(smc + G1_SB);
    char* sAhi = smc + G1_AHI;
    char* sAlo = smc + G1_ALO;
    char* sBhi = smc + G1_BHI;
    char* sBlo = smc + G1_BLO;

    const int tid = threadIdx.x;
    const int row0 = blockIdx.x * 128;

    if (tid < 64) { sa[tid] = g_scale[0][tid]; ssh[tid] = g_shift[0][tid]; sb[tid] = bbias[tid]; }
    {
        const uint4* shi = (const uint4*)g_whi[1];
        const uint4* slo = (const uint4*)g_wlo[1];
        uint4* dhi = (uint4*)sBhi;
        uint4* dlo = (uint4*)sBlo;
        for (int i = tid; i < 576; i += 128) { dhi[i] = shi[i]; dlo[i] = slo[i]; }
    }
    __syncthreads();   // sa/ssh visible

    {
        const int r = tid;
        const float* hrow = &g_h0[(size_t)(row0 + r)*64];
#pragma unroll
        for (int kk = 0; kk < 64; kk += 8) {
            float4 u0 = *(const float4*)&hrow[kk];
            float4 u1 = *(const float4*)&hrow[kk+4];
            float v[8] = {u0.x,u0.y,u0.z,u0.w,u1.x,u1.y,u1.z,u1.w};
#pragma unroll
            for (int j = 0; j < 8; j++) v[j] = fmaxf(0.f, fmaf(sa[kk+j], v[j], ssh[kk+j]));
            uint32_t whi[4], wlo[4];
#pragma unroll
            for (int j = 0; j < 4; j++) split_pack(v[2*j], v[2*j+1], whi[j], wlo[j]);
            *(uint4*)(sAhi + r*ASTRIDE + kk*2) = make_uint4(whi[0],whi[1],whi[2],whi[3]);
            *(uint4*)(sAlo + r*ASTRIDE + kk*2) = make_uint4(wlo[0],wlo[1],wlo[2],wlo[3]);
        }
    }
    __syncthreads();

    const int lane = tid & 31, w = tid >> 5;
    const uint32_t aHi = smem_u32(sAhi), aLo = smem_u32(sAlo);
    const uint32_t bHi = smem_u32(sBhi), bLo = smem_u32(sBlo);
    const int aRow = w*32 + (lane & 15);
    const int aCol = (lane >> 4) * 8;
    const int bN   = (lane & 7) + ((lane & 16) ? 8 : 0);
    const int bK   = (lane & 8) ? 8 : 0;

    float acc[2][8][4];
#pragma unroll
    for (int i=0;i<2;i++)
#pragma unroll
        for (int j=0;j<8;j++)
#pragma unroll
            for (int q=0;q<4;q++) acc[i][j][q]=0.f;

#pragma unroll
    for (int kk = 0; kk < 64; kk += 16) {
        uint32_t ahi[2][4], alo[2][4];
#pragma unroll
        for (int mt = 0; mt < 2; mt++) {
            ldsm_x4(ahi[mt], aHi + (aRow + mt*16)*ASTRIDE + (kk + aCol)*2);
            ldsm_x4(alo[mt], aLo + (aRow + mt*16)*ASTRIDE + (kk + aCol)*2);
        }
        uint32_t bhi[4][4], blo[4][4];
#pragma unroll
        for (int p = 0; p < 4; p++) {
            ldsm_x4(bhi[p], bHi + (p*16 + bN)*ASTRIDE + (kk + bK)*2);
            ldsm_x4(blo[p], bLo + (p*16 + bN)*ASTRIDE + (kk + bK)*2);
        }
#pragma unroll
        for (int mt = 0; mt < 2; mt++)
#pragma unroll
            for (int nt = 0; nt < 8; nt++) {
                const uint32_t* bh = &bhi[nt>>1][(nt&1)*2];
                const uint32_t* bl = &blo[nt>>1][(nt&1)*2];
                mma16816(acc[mt][nt], ahi[mt], bh);
                mma16816(acc[mt][nt], ahi[mt], bl);
                mma16816(acc[mt][nt], alo[mt], bh);
            }
    }

    const int qr = lane >> 2;
    const int qc = (lane & 3) * 2;
#pragma unroll
    for (int mt = 0; mt < 2; mt++) {
        size_t rbase = (size_t)(row0 + w*32 + mt*16 + qr);
#pragma unroll
        for (int nt = 0; nt < 8; nt++) {
            int c0 = nt*8 + qc, c1 = c0 + 1;
            *(float2*)&g_h1[rbase*64 + c0]     = make_float2(acc[mt][nt][0] + sb[c0], acc[mt][nt][1] + sb[c1]);
            *(float2*)&g_h1[(rbase+8)*64 + c0] = make_float2(acc[mt][nt][2] + sb[c0], acc[mt][nt][3] + sb[c1]);
        }
    }

    // fused partials over L2-hot h1 tile
    __syncthreads();
    {
        float* ps = (float*)(smc + G1_AHI);
        float* pq = ps + 512;
        const int c4 = (tid & 15) * 4, rg = tid >> 4;
        float s[4] = {0,0,0,0}, q[4] = {0,0,0,0};
#pragma unroll 4
        for (int k = 0; k < 16; k++) {
            float4 v = *(const float4*)&g_h1[(size_t)(row0 + rg + k*8)*64 + c4];
            s[0]+=v.x; q[0]=fmaf(v.x,v.x,q[0]);
            s[1]+=v.y; q[1]=fmaf(v.y,v.y,q[1]);
            s[2]+=v.z; q[2]=fmaf(v.z,v.z,q[2]);
            s[3]+=v.w; q[3]=fmaf(v.w,v.w,q[3]);
        }
#pragma unroll
        for (int j = 0; j < 4; j++) { ps[rg*64 + c4 + j] = s[j]; pq[rg*64 + c4 + j] = q[j]; }
        __syncthreads();
        if (tid < 64) {
            float ts = 0.f, tq = 0.f;
#pragma unroll
            for (int g = 0; g < 8; g++) { ts += ps[g*64 + tid]; tq += pq[g*64 + tid]; }
            g_psum[blockIdx.x*64 + tid] = ts;
            g_psq [blockIdx.x*64 + tid] = tq;
        }
    }
}

// gemm2 smem layout (256 threads, N=128)
#define G2_SA    0
#define G2_SS    256
#define G2_SB    512      // 128 floats -> 1024
#define G2_AHI   1024     // -> 19456
#define G2_ALO   19456    // -> 37888
#define G2_BHI   37888    // 128*144=18432 -> 56320
#define G2_BLO   56320    // -> 74752
#define G2_STAGE 1024     // overlaps A/B after mainloop: 128*130*4 = 66560 -> 67584
#define G2_PS    67584
#define G2_PQ    68608
#define G2_SM    74752

__global__ __launch_bounds__(256)
void gemm2_kernel(const float* __restrict__ bbias)
{
    extern __shared__ char smc[];
    float* sa  = (float*)(smc + G2_SA);
    float* ssh = (float*)(smc + G2_SS);
    float* sb  = (float*)(smc + G2_SB);
    char* sAhi = smc + G2_AHI;
    char* sAlo = smc + G2_ALO;
    char* sBhi = smc + G2_BHI;
    char* sBlo = smc + G2_BLO;

    const int tid = threadIdx.x;
    const int row0 = blockIdx.x * 128;

    if (tid < 64)  { sa[tid] = g_scale[1][tid]; ssh[tid] = g_shift[1][tid]; }
    if (tid < 128) sb[tid] = bbias[tid];
    {
        const uint4* shi = (const uint4*)g_whi[2];
        const uint4* slo = (const uint4*)g_wlo[2];
        uint4* dhi = (uint4*)sBhi;
        uint4* dlo = (uint4*)sBlo;
        for (int i = tid; i < 1152; i += 256) { dhi[i] = shi[i]; dlo[i] = slo[i]; }  // 128*144/16
    }
    __syncthreads();

    {
        const int r = tid >> 1;
        const int kbase = (tid & 1) * 32;
        const float* hrow = &g_h1[(size_t)(row0 + r)*64];
#pragma unroll
        for (int kk = kbase; kk < kbase + 32; kk += 8) {
            float4 u0 = *(const float4*)&hrow[kk];
            float4 u1 = *(const float4*)&hrow[kk+4];
            float v[8] = {u0.x,u0.y,u0.z,u0.w,u1.x,u1.y,u1.z,u1.w};
#pragma unroll
            for (int j = 0; j < 8; j++) v[j] = fmaxf(0.f, fmaf(sa[kk+j], v[j], ssh[kk+j]));
            uint32_t whi[4], wlo[4];
#pragma unroll
            for (int j = 0; j < 4; j++) split_pack(v[2*j], v[2*j+1], whi[j], wlo[j]);
            *(uint4*)(sAhi + r*ASTRIDE + kk*2) = make_uint4(whi[0],whi[1],whi[2],whi[3]);
            *(uint4*)(sAlo + r*ASTRIDE + kk*2) = make_uint4(wlo[0],wlo[1],wlo[2],wlo[3]);
        }
    }
    __syncthreads();

    const int lane = tid & 31, w = tid >> 5;   // 8 warps, warp = 16 rows
    const uint32_t aHi = smem_u32(sAhi), aLo = smem_u32(sAlo);
    const uint32_t bHi = smem_u32(sBhi), bLo = smem_u32(sBlo);
    const int aRow = w*16 + (lane & 15);
    const int aCol = (lane >> 4) * 8;
    const int bN   = (lane & 7) + ((lane & 16) ? 8 : 0);
    const int bK   = (lane & 8) ? 8 : 0;

    float acc[16][4];
#pragma unroll
    for (int j=0;j<16;j++)
#pragma unroll
        for (int q=0;q<4;q++) acc[j][q]=0.f;

#pragma unroll
    for (int kk = 0; kk < 64; kk += 16) {
        uint32_t ahi[4], alo[4];
        ldsm_x4(ahi, aHi + aRow*ASTRIDE + (kk + aCol)*2);
        ldsm_x4(alo, aLo + aRow*ASTRIDE + (kk + aCol)*2);
        uint32_t bhi[8][4], blo[8][4];
#pragma unroll
        for (int p = 0; p < 8; p++) {
            ldsm_x4(bhi[p], bHi + (p*16 + bN)*ASTRIDE + (kk + bK)*2);
            ldsm_x4(blo[p], bLo + (p*16 + bN)*ASTRIDE + (kk + bK)*2);
        }
#pragma unroll
        for (int nt = 0; nt < 16; nt++) {
            const uint32_t* bh = &bhi[nt>>1][(nt&1)*2];
            const uint32_t* bl = &blo[nt>>1][(nt&1)*2];
            mma16816(acc[nt], ahi, bh);
            mma16816(acc[nt], ahi, bl);
            mma16816(acc[nt], alo, bh);
        }
    }
    __syncthreads();     // A/B planes dead; stage overlaps them

    float* stage = (float*)(smc + G2_STAGE);
    {
        const int qr = lane >> 2;
        const int qc = (lane & 3) * 2;
        int r0 = w*16 + qr;
#pragma unroll
        for (int nt = 0; nt < 16; nt++) {
            int c0 = nt*8 + qc;
            *(float2*)&stage[r0*130 + c0]      = make_float2(acc[nt][0], acc[nt][1]);
            *(float2*)&stage[(r0+8)*130 + c0]  = make_float2(acc[nt][2], acc[nt][3]);
        }
    }
    __syncthreads();

    {
        float* ps = (float*)(smc + G2_PS);
        float* pq = (float*)(smc + G2_PQ);
        const int c = tid & 127;
        const int half = tid >> 7;
        const float bc = sb[c];
        float s = 0.f, q = 0.f;
        float mx[2] = {-3.4e38f, -3.4e38f}, mn[2] = {3.4e38f, 3.4e38f};
#pragma unroll 4
        for (int rr = 0; rr < 64; rr++) {
            float v = stage[(half*64 + rr)*130 + c] + bc;
            s += v; q = fmaf(v, v, q);
            int g = rr >> 5;
            mx[g] = fmaxf(mx[g], v); mn[g] = fminf(mn[g], v);
        }
        ps[half*128 + c] = s;
        pq[half*128 + c] = q;
#pragma unroll
        for (int g = 0; g < 2; g++) {
            size_t grp = (size_t)blockIdx.x*4 + half*2 + g;
            g_gmax[grp*128 + c] = mx[g];
            g_gmin[grp*128 + c] = mn[g];
        }
        __syncthreads();
        if (tid < 128) {
            g_psum[blockIdx.x*128 + tid] = ps[tid] + ps[128 + tid];
            g_psq [blockIdx.x*128 + tid] = pq[tid] + pq[128 + tid];
        }
    }
}

// =====================================================================
// fold: BN -> per-channel affine (a, c)
// =====================================================================
__global__ __launch_bounds__(256)
void fold_kernel(const float* __restrict__ g, const float* __restrict__ be,
                 int layer, int nch)
{
    __shared__ double ssum[256], ssq[256];
    const int ch = blockIdx.x;
    const int t  = threadIdx.x;

    double s = 0.0, q = 0.0;
    for (int b = t; b < NBLK; b += 256) {
        s += (double)g_psum[b*nch + ch];
        q += (double)g_psq [b*nch + ch];
    }
    ssum[t] = s; ssq[t] = q;
    __syncthreads();
#pragma unroll
    for (int off = 128; off > 0; off >>= 1) {
        if (t < off) { ssum[t] += ssum[t+off]; ssq[t] += ssq[t+off]; }
        __syncthreads();
    }
    if (t == 0) {
        const double M = (double)MROWS;
        double mu  = ssum[0] / M;
        double var = ssq[0] / M - mu*mu;
        float rs = (float)(1.0 / sqrt(var + 1e-5));
        float a  = g[ch] * rs;
        float c  = be[ch] - (float)mu * a;
        g_scale[layer][ch] = a;
        g_shift[layer][ch] = c;
    }
}

// =====================================================================
// Final: relu(a * (a>=0 ? gmax : gmin) + c)
// =====================================================================
__global__ void final_kernel(float* __restrict__ out)
{
    int grp = blockIdx.x, ch = threadIdx.x;
    float a = g_scale[2][ch], c = g_shift[2][ch];
    float h = (a >= 0.f) ? g_gmax[(size_t)grp*128 + ch] : g_gmin[(size_t)grp*128 + ch];
    out[OUT_XYZ_ELEMS + (size_t)grp*128 + ch] = fmaxf(0.f, fmaf(a, h, c));
}

// =====================================================================
extern "C" void kernel_launch(void* const* d_in, const int* in_sizes, int n_in,
                              void* d_out, int out_size)
{
    const float* xyz    = (const float*)d_in[0];
    const float* points = (const float*)d_in[1];
    const float* w0  = (const float*)d_in[2];
    const float* b0  = (const float*)d_in[3];
    const float* g0  = (const float*)d_in[4];
    const float* be0 = (const float*)d_in[5];
    const float* w1  = (const float*)d_in[6];
    const float* b1  = (const float*)d_in[7];
    const float* g1  = (const float*)d_in[8];
    const float* be1 = (const float*)d_in[9];
    const float* w2  = (const float*)d_in[10];
    const float* b2  = (const float*)d_in[11];
    const float* g2  = (const float*)d_in[12];
    const float* be2 = (const float*)d_in[13];
    float* out = (float*)d_out;

    const int FPS_SM = NPTS*3*4;             // 49152
    cudaFuncSetAttribute(fps_kernel,   cudaFuncAttributeMaxDynamicSharedMemorySize, FPS_SM);
    cudaFuncSetAttribute(gemm0_kernel, cudaFuncAttributeMaxDynamicSharedMemorySize, G0_SM);
    cudaFuncSetAttribute(gemm1_kernel, cudaFuncAttributeMaxDynamicSharedMemorySize, G1_SM);
    cudaFuncSetAttribute(gemm2_kernel, cudaFuncAttributeMaxDynamicSharedMemorySize, G2_SM);

    prep_kernel<<<64, 256>>>(w0, w1, w2);                           // 0
    fps_kernel<<<BATCH, 1024, FPS_SM>>>(xyz, out);                  // 1
    ballquery_kernel<<<(NGROUP*32)/128, 128>>>(xyz, out);           // 2
    gemm0_kernel<<<NBLK, 128, G0_SM>>>(xyz, points, w0, b0, out);   // 3
    fold_kernel<<<64, 256>>>(g0, be0, 0, 64);                       // 4
    gemm1_kernel<<<NBLK, 128, G1_SM>>>(b1);                         // 5  <- ncu -s 5
    fold_kernel<<<64, 256>>>(g1, be1, 1, 64);                       // 6
    gemm2_kernel<<<NBLK, 256, G2_SM>>>(b2);                         // 7
    fold_kernel<<<128, 256>>>(g2, be2, 2, 128);                     // 8
    final_kernel<<<NGROUP, 128>>>(out);                             // 9
}